// round 1
// baseline (speedup 1.0000x reference)
#include <cuda_runtime.h>
#include <math.h>

#define DD 200
#define NTY 4
#define NET 38
#define NT1 39
#define BB 256
#define LL 1024
#define EE 262144
#define NN 51200
#define NCOMBO 608
#define TOTROWS (EE + NN)

// ------------------------- scratch (static device memory) -------------------------
__device__ float d_coeff[NT1 * NN];          // +/- incidence counts per (etype, node)
__device__ float d_sums[NT1 * DD];
__device__ int   d_cntT[NT1];
__device__ int   d_cntE[NCOMBO];
__device__ int   d_cntN[NTY];
__device__ int   d_combo[EE];
__device__ int   d_cntSrc[NN];
__device__ float d_meanT[NT1 * DD];
__device__ float d_preE[NCOMBO * DD];
__device__ float d_preS[NTY * DD];
__device__ float d_embE[NCOMBO * DD];
__device__ float d_embS[NTY * DD];
__device__ float d_h2[NCOMBO * DD];
__device__ float d_Rtab[NCOMBO * DD];
__device__ float d_bn1m[DD], d_bn1r[DD], d_bn2m[DD], d_bn2r[DD], d_bn3m[DD], d_bn3r[DD];
__device__ float d_qv[BB * DD];
__device__ float d_P[BB * NCOMBO];
__device__ float d_Wt[BB * NCOMBO];
__device__ float d_upd[BB * DD];
__device__ float d_UK[BB * DD];
__device__ float d_UM[BB * DD];
__device__ float d_SK[NTY * DD];
__device__ float d_SM[NTY * DD];
__device__ float d_Wcat[DD * 600];
__device__ float d_XKMQ[(size_t)NN * 600];   // per-node [XK | XM | XQ]
__device__ float d_ex[(size_t)TOTROWS * 4];
__device__ float d_den[NN * 4];
__device__ float d_aggr[(size_t)NN * DD];
__device__ float d_Y1[(size_t)NN * DD];
__device__ float d_colsum[DD], d_colsum2[DD];

// ------------------------- zero init -------------------------
__global__ void k_zero() {
    long long i0 = (long long)blockIdx.x * blockDim.x + threadIdx.x;
    long long st = (long long)gridDim.x * blockDim.x;
    for (long long i = i0; i < (long long)NN * DD; i += st) d_aggr[i] = 0.f;
    for (long long i = i0; i < (long long)NT1 * NN; i += st) d_coeff[i] = 0.f;
    for (long long i = i0; i < (long long)NN * 4; i += st) d_den[i] = 0.f;
    for (long long i = i0; i < NT1 * DD; i += st) d_sums[i] = 0.f;
    for (long long i = i0; i < NCOMBO; i += st) d_cntE[i] = 0;
    for (long long i = i0; i < NT1; i += st) d_cntT[i] = 0;
    for (long long i = i0; i < NTY; i += st) d_cntN[i] = 0;
    for (long long i = i0; i < DD; i += st) { d_colsum[i] = 0.f; d_colsum2[i] = 0.f; }
}

// ------------------------- histograms -------------------------
__global__ void k_nodehist(const int* __restrict__ ntp) {
    int n = blockIdx.x * blockDim.x + threadIdx.x;
    if (n >= NN) return;
    d_cntSrc[n] = 1;                       // self loop
    atomicAdd(&d_cntN[ntp[n]], 1);
}

__global__ void k_edgehist(const int* __restrict__ ei, const int* __restrict__ et,
                           const int* __restrict__ ntp) {
    int e = blockIdx.x * blockDim.x + threadIdx.x;
    if (e >= EE) return;
    int s  = ei[e];
    int dd = ei[EE + e];
    int t  = et[e];
    atomicAdd(&d_coeff[t * NN + dd],  1.f);
    atomicAdd(&d_coeff[t * NN + s],  -1.f);
    atomicAdd(&d_cntT[t], 1);
    int c = (t << 4) | (ntp[s] << 2) | ntp[dd];
    d_combo[e] = c;
    atomicAdd(&d_cntE[c], 1);
    atomicAdd(&d_cntSrc[s], 1);
}

// ------------------------- segment sums via coeff @ x -------------------------
__global__ void k_segsum(const float* __restrict__ x) {
    __shared__ float acc[NT1 * DD];
    __shared__ float cf[NT1];
    for (int i = threadIdx.x; i < NT1 * DD; i += blockDim.x) acc[i] = 0.f;
    __syncthreads();
    int n0 = blockIdx.x * 128;
    for (int n = n0; n < n0 + 128; n++) {
        if (threadIdx.x < NT1) cf[threadIdx.x] = d_coeff[threadIdx.x * NN + n];
        __syncthreads();
        if (threadIdx.x < DD) {
            float xv = x[(size_t)n * DD + threadIdx.x];
            for (int t = 0; t < NT1; t++) acc[t * DD + threadIdx.x] += cf[t] * xv;
        }
        __syncthreads();
    }
    for (int i = threadIdx.x; i < NT1 * DD; i += blockDim.x)
        if (acc[i] != 0.f) atomicAdd(&d_sums[i], acc[i]);
}

__global__ void k_meanT() {
    int i = blockIdx.x * blockDim.x + threadIdx.x;
    if (i >= NT1 * DD) return;
    int t = i / DD;
    float c = (float)d_cntT[t];
    if (c < 1.f) c = 1.f;
    d_meanT[i] = d_sums[i] / c;
}

// ------------------------- combo tables -------------------------
__global__ void k_tables(const float* __restrict__ We1, const float* __restrict__ be1) {
    int c = blockIdx.x, d = threadIdx.x;
    if (d >= DD) return;
    if (c < NCOMBO) {
        int t = c >> 4, a = (c >> 2) & 3, b = c & 3;
        d_preE[c * DD + d] = We1[t * DD + d] + We1[(NT1 + a) * DD + d]
                           + We1[(NT1 + NTY + b) * DD + d] + be1[d];
    } else {
        int t = c - NCOMBO;
        d_preS[t * DD + d] = We1[NET * DD + d] + We1[(NT1 + t) * DD + d]
                           + We1[(NT1 + NTY + t) * DD + d] + be1[d];
    }
}

__global__ void k_bnstat1() {
    int d = threadIdx.x;
    if (d >= DD) return;
    double s = 0.0, s2 = 0.0;
    for (int c = 0; c < NCOMBO; c++) {
        double w = (double)d_cntE[c], v = (double)d_preE[c * DD + d];
        s += w * v; s2 += w * v * v;
    }
    for (int t = 0; t < NTY; t++) {
        double w = (double)d_cntN[t], v = (double)d_preS[t * DD + d];
        s += w * v; s2 += w * v * v;
    }
    double m = s / (double)TOTROWS;
    double var = s2 / (double)TOTROWS - m * m;
    d_bn1m[d] = (float)m;
    d_bn1r[d] = rsqrtf((float)var + 1e-5f);
}

__global__ void k_emb(const float* __restrict__ We2, const float* __restrict__ be2,
                      const float* __restrict__ g, const float* __restrict__ bt) {
    int c = blockIdx.x, d = threadIdx.x;
    __shared__ float a[DD];
    const float* srow = (c < NCOMBO) ? &d_preE[c * DD] : &d_preS[(c - NCOMBO) * DD];
    if (d < DD) {
        float v = (srow[d] - d_bn1m[d]) * d_bn1r[d] * g[d] + bt[d];
        a[d] = fmaxf(v, 0.f);
    }
    __syncthreads();
    if (d < DD) {
        float acc = 0.f;
        for (int k = 0; k < DD; k++) acc += a[k] * We2[k * DD + d];
        float* dst = (c < NCOMBO) ? &d_embE[c * DD] : &d_embS[(c - NCOMBO) * DD];
        dst[d] = acc + be2[d];
    }
}

__global__ void k_h2pre(const float* __restrict__ Wa1, const float* __restrict__ ba1) {
    int c = blockIdx.x, d = threadIdx.x;
    __shared__ float e[DD], mt[DD];
    int t = c >> 4;
    if (d < DD) { e[d] = d_embE[c * DD + d]; mt[d] = d_meanT[t * DD + d]; }
    __syncthreads();
    if (d < DD) {
        float acc = ba1[d];
        for (int k = 0; k < DD; k++) acc += e[k] * Wa1[k * DD + d];
        for (int k = 0; k < DD; k++) acc += mt[k] * Wa1[(DD + k) * DD + d];
        d_h2[c * DD + d] = acc;
    }
}

__global__ void k_bnstat2() {
    int d = threadIdx.x;
    if (d >= DD) return;
    double s = 0.0, s2 = 0.0;
    for (int c = 0; c < NCOMBO; c++) {
        double w = (double)d_cntE[c], v = (double)d_h2[c * DD + d];
        s += w * v; s2 += w * v * v;
    }
    double m = s / (double)EE;
    double var = s2 / (double)EE - m * m;
    d_bn2m[d] = (float)m;
    d_bn2r[d] = rsqrtf((float)var + 1e-5f);
}

__global__ void k_Rtab(const float* __restrict__ Wa2, const float* __restrict__ ba2,
                       const float* __restrict__ g, const float* __restrict__ bt) {
    int c = blockIdx.x, d = threadIdx.x;
    __shared__ float a[DD];
    if (d < DD) {
        float v = (d_h2[c * DD + d] - d_bn2m[d]) * d_bn2r[d] * g[d] + bt[d];
        a[d] = fmaxf(v, 0.f);
    }
    __syncthreads();
    if (d < DD) {
        float acc = 0.f;
        for (int k = 0; k < DD; k++) acc += a[k] * Wa2[k * DD + d];
        d_Rtab[c * DD + d] = acc + ba2[d];
    }
}

// ------------------------- graph attention -------------------------
__global__ void k_q(const float* __restrict__ sent, const float* __restrict__ Watt) {
    int b = blockIdx.x, d = threadIdx.x;
    __shared__ float s[DD];
    if (d < DD) s[d] = sent[b * DD + d];
    __syncthreads();
    if (d < DD) {
        float acc = 0.f;
        for (int k = 0; k < DD; k++) acc += s[k] * Watt[k * DD + d];
        d_qv[b * DD + d] = acc;
    }
}

__global__ void k_P() {
    int b = blockIdx.x, tid = threadIdx.x, lane = tid & 31, w = tid >> 5;
    __shared__ float q[DD];
    for (int i = tid; i < DD; i += blockDim.x)
        q[i] = d_qv[b * DD + i] * 0.07071067811865475f;  // 1/sqrt(200)
    __syncthreads();
    for (int c = w; c < NCOMBO; c += 8) {
        float p = 0.f;
        for (int k = lane; k < DD; k += 32) p += q[k] * d_Rtab[c * DD + k];
        for (int o = 16; o > 0; o >>= 1) p += __shfl_down_sync(0xffffffffu, p, o);
        if (lane == 0) d_P[b * NCOMBO + c] = p;
    }
}

__global__ void k_graphsm() {
    int b = blockIdx.x, tid = threadIdx.x;
    __shared__ float Pb[NCOMBO];
    __shared__ float Wacc[NCOMBO];
    __shared__ float red[256];
    for (int i = tid; i < NCOMBO; i += 256) { Pb[i] = d_P[b * NCOMBO + i]; Wacc[i] = 0.f; }
    __syncthreads();
    int cid[4]; float sc[4]; float lmax = -1e30f;
#pragma unroll
    for (int j = 0; j < 4; j++) {
        int e = b * LL + tid + j * 256;
        cid[j] = d_combo[e];
        sc[j] = Pb[cid[j]];
        lmax = fmaxf(lmax, sc[j]);
    }
    red[tid] = lmax; __syncthreads();
    for (int s = 128; s > 0; s >>= 1) { if (tid < s) red[tid] = fmaxf(red[tid], red[tid + s]); __syncthreads(); }
    float bmax = red[0]; __syncthreads();
    float lsum = 0.f;
#pragma unroll
    for (int j = 0; j < 4; j++) { sc[j] = expf(sc[j] - bmax); lsum += sc[j]; }
    red[tid] = lsum; __syncthreads();
    for (int s = 128; s > 0; s >>= 1) { if (tid < s) red[tid] += red[tid + s]; __syncthreads(); }
    float inv = 1.f / red[0]; __syncthreads();
#pragma unroll
    for (int j = 0; j < 4; j++) atomicAdd(&Wacc[cid[j]], sc[j] * inv);
    __syncthreads();
    for (int i = tid; i < NCOMBO; i += 256) d_Wt[b * NCOMBO + i] = Wacc[i];
}

__global__ void k_upd() {
    int b = blockIdx.x, d = threadIdx.x;
    __shared__ float w[NCOMBO];
    for (int i = d; i < NCOMBO; i += blockDim.x) w[i] = d_Wt[b * NCOMBO + i];
    __syncthreads();
    if (d < DD) {
        float acc = 0.f;
        for (int c = 0; c < NCOMBO; c++) acc += w[c] * d_Rtab[c * DD + d];
        d_upd[b * DD + d] = acc;
    }
}

__global__ void k_ukum(const float* __restrict__ Wk, const float* __restrict__ Wm) {
    int id = blockIdx.x, d = threadIdx.x;
    __shared__ float s[DD];
    const float* srow; float *ok, *om;
    if (id < BB) { srow = &d_upd[id * DD]; ok = &d_UK[id * DD]; om = &d_UM[id * DD]; }
    else { int t = id - BB; srow = &d_embS[t * DD]; ok = &d_SK[t * DD]; om = &d_SM[t * DD]; }
    if (d < DD) s[d] = srow[d];
    __syncthreads();
    if (d < DD) {
        float ak = 0.f, am = 0.f;
        for (int k = 0; k < DD; k++) {
            float sv = s[k];
            ak += sv * Wk[(DD + k) * DD + d];
            am += sv * Wm[(DD + k) * DD + d];
        }
        ok[d] = ak; om[d] = am;
    }
}

// ------------------------- assemble Wcat, big GEMM -------------------------
__global__ void k_wcat(const float* __restrict__ Wk, const float* __restrict__ Wm,
                       const float* __restrict__ Wq) {
    int i = blockIdx.x * blockDim.x + threadIdx.x;
    if (i >= DD * 600) return;
    int k = i / 600, c = i % 600;
    float v = (c < DD) ? Wk[k * DD + c]
            : (c < 2 * DD) ? Wm[k * DD + (c - DD)]
            : Wq[k * DD + (c - 2 * DD)];
    d_Wcat[i] = v;
}

// generic tiled fp32 GEMM: C = op(A) @ B (+ bias), op = optional BN+relu on A rows
#define BM 64
#define BN_ 64
#define BK 8
__global__ void k_gemm(int M, int N, int K,
                       const float* __restrict__ A, int lda,
                       const float* __restrict__ B, int ldb,
                       float* __restrict__ C, int ldc,
                       const float* __restrict__ bias,
                       const float* __restrict__ bnm, const float* __restrict__ bnr,
                       const float* __restrict__ bng, const float* __restrict__ bnb) {
    __shared__ float As[BK][BM];
    __shared__ float Bs[BK][BN_];
    int tid = threadIdx.x;
    int tx = tid % 16, ty = tid / 16;
    int row0 = blockIdx.y * BM, col0 = blockIdx.x * BN_;
    float acc[4][4] = {};
    for (int k0 = 0; k0 < K; k0 += BK) {
#pragma unroll
        for (int i = 0; i < 2; i++) {
            int idx = tid + i * 256;
            int m = idx / BK, kk = idx % BK;
            int gm = row0 + m, gk = k0 + kk;
            float v = 0.f;
            if (gm < M && gk < K) {
                v = A[(size_t)gm * lda + gk];
                if (bnm) {
                    v = (v - bnm[gk]) * bnr[gk] * bng[gk] + bnb[gk];
                    v = fmaxf(v, 0.f);
                }
            }
            As[kk][m] = v;
        }
#pragma unroll
        for (int i = 0; i < 2; i++) {
            int idx = tid + i * 256;
            int kk = idx / BN_, n = idx % BN_;
            int gk = k0 + kk, gn = col0 + n;
            Bs[kk][n] = (gk < K && gn < N) ? B[(size_t)gk * ldb + gn] : 0.f;
        }
        __syncthreads();
#pragma unroll
        for (int kk = 0; kk < BK; kk++) {
            float a[4], b[4];
#pragma unroll
            for (int i = 0; i < 4; i++) a[i] = As[kk][ty * 4 + i];
#pragma unroll
            for (int j = 0; j < 4; j++) b[j] = Bs[kk][tx * 4 + j];
#pragma unroll
            for (int i = 0; i < 4; i++)
#pragma unroll
                for (int j = 0; j < 4; j++) acc[i][j] += a[i] * b[j];
        }
        __syncthreads();
    }
#pragma unroll
    for (int i = 0; i < 4; i++) {
        int gm = row0 + ty * 4 + i;
        if (gm >= M) continue;
#pragma unroll
        for (int j = 0; j < 4; j++) {
            int gn = col0 + tx * 4 + j;
            if (gn >= N) continue;
            float v = acc[i][j];
            if (bias) v += bias[gn];
            C[(size_t)gm * ldc + gn] = v;
        }
    }
}

// ------------------------- edge attention passes -------------------------
__global__ void k_D1(const int* __restrict__ ei, const int* __restrict__ ntp,
                     const float* __restrict__ bq, const float* __restrict__ bk) {
    int warp = (blockIdx.x * blockDim.x + threadIdx.x) >> 5;
    int lane = threadIdx.x & 31;
    if (warp >= TOTROWS) return;
    int i = warp;
    int s, dd; const float* kadd;
    if (i < EE) { s = ei[i]; dd = ei[EE + i]; kadd = &d_UK[(i >> 10) * DD]; }
    else { int n = i - EE; s = n; dd = n; kadd = &d_SK[ntp[n] * DD]; }
    const float* qrow = &d_XKMQ[(size_t)s * 600 + 400];
    const float* krow = &d_XKMQ[(size_t)dd * 600];
    const float invs = 0.1414213562373095f;  // 1/sqrt(50)
#pragma unroll
    for (int h = 0; h < 4; h++) {
        float p = 0.f;
        if (lane < 25) {
            int d0 = h * 50 + lane * 2;
            float2 q2 = *(const float2*)(qrow + d0);
            float2 k2 = *(const float2*)(krow + d0);
            float2 a2 = *(const float2*)(kadd + d0);
            float2 bq2 = *(const float2*)(bq + d0);
            float2 bk2 = *(const float2*)(bk + d0);
            float qa = (q2.x + bq2.x) * invs, qb = (q2.y + bq2.y) * invs;
            float ka = k2.x + a2.x + bk2.x, kb = k2.y + a2.y + bk2.y;
            p = qa * ka + qb * kb;
        }
        for (int o = 16; o > 0; o >>= 1) p += __shfl_down_sync(0xffffffffu, p, o);
        if (lane == 0) {
            float exv = expf(p);   // shift-invariant softmax: max-subtract omitted (|p| << 1)
            d_ex[(size_t)i * 4 + h] = exv;
            atomicAdd(&d_den[s * 4 + h], exv);
        }
    }
}

__global__ void k_D2(const int* __restrict__ ei, const int* __restrict__ ntp,
                     const float* __restrict__ bm) {
    int warp = (blockIdx.x * blockDim.x + threadIdx.x) >> 5;
    int lane = threadIdx.x & 31;
    if (warp >= TOTROWS) return;
    int i = warp;
    int s, j, dn; const float* madd;
    if (i < EE) { s = ei[i]; j = s; dn = ei[EE + i]; madd = &d_UM[(i >> 10) * DD]; }
    else { int n = i - EE; s = n; j = n; dn = n; madd = &d_SM[ntp[n] * DD]; }
    float av = 0.f;
    if (lane < 4)
        av = d_ex[(size_t)i * 4 + lane] / d_den[s * 4 + lane] * (float)d_cntSrc[s];
    float a0 = __shfl_sync(0xffffffffu, av, 0);
    float a1 = __shfl_sync(0xffffffffu, av, 1);
    float a2v = __shfl_sync(0xffffffffu, av, 2);
    float a3 = __shfl_sync(0xffffffffu, av, 3);
    const float* mrow = &d_XKMQ[(size_t)j * 600 + 200];
    float* arow = &d_aggr[(size_t)dn * DD];
    for (int u = lane; u < 50; u += 32) {
        int d0 = u * 4;
        float4 xm = *(const float4*)(mrow + d0);
        float4 ad = *(const float4*)(madd + d0);
        float4 bb = *(const float4*)(bm + d0);
        float v[4] = { xm.x + ad.x + bb.x, xm.y + ad.y + bb.y,
                       xm.z + ad.z + bb.z, xm.w + ad.w + bb.w };
#pragma unroll
        for (int e2 = 0; e2 < 4; e2++) {
            int didx = d0 + e2;
            float al = didx < 50 ? a0 : didx < 100 ? a1 : didx < 150 ? a2v : a3;
            atomicAdd(arow + didx, v[e2] * al);
        }
    }
}

// ------------------------- output BN stats -------------------------
__global__ void k_colstat() {
    int d = threadIdx.x;
    if (d >= DD) return;
    int r0 = blockIdx.x * 256;
    float s = 0.f, s2 = 0.f;
    for (int r = r0; r < r0 + 256; r++) {
        float v = d_Y1[(size_t)r * DD + d];
        s += v; s2 += v * v;
    }
    atomicAdd(&d_colsum[d], s);
    atomicAdd(&d_colsum2[d], s2);
}

__global__ void k_stat3() {
    int d = threadIdx.x;
    if (d >= DD) return;
    float m = d_colsum[d] / (float)NN;
    float var = d_colsum2[d] / (float)NN - m * m;
    d_bn3m[d] = m;
    d_bn3r[d] = rsqrtf(var + 1e-5f);
}

// ------------------------- launch -------------------------
extern "C" void kernel_launch(void* const* d_in, const int* in_sizes, int n_in,
                              void* d_out, int out_size) {
    const float* x    = (const float*)d_in[0];
    const float* sent = (const float*)d_in[2];
    const float* We1  = (const float*)d_in[3];
    const float* be1  = (const float*)d_in[4];
    const float* ge1  = (const float*)d_in[5];
    const float* bte1 = (const float*)d_in[6];
    const float* We2  = (const float*)d_in[7];
    const float* be2  = (const float*)d_in[8];
    const float* Wa1  = (const float*)d_in[9];
    const float* ba1  = (const float*)d_in[10];
    const float* ga1  = (const float*)d_in[11];
    const float* bta1 = (const float*)d_in[12];
    const float* Wa2  = (const float*)d_in[13];
    const float* ba2  = (const float*)d_in[14];
    const float* Watt = (const float*)d_in[15];
    const float* Wk   = (const float*)d_in[16];
    const float* bk   = (const float*)d_in[17];
    const float* Wm   = (const float*)d_in[18];
    const float* bm   = (const float*)d_in[19];
    const float* Wq   = (const float*)d_in[20];
    const float* bq   = (const float*)d_in[21];
    const float* Wo1  = (const float*)d_in[22];
    const float* bo1  = (const float*)d_in[23];
    const float* go1  = (const float*)d_in[24];
    const float* bto1 = (const float*)d_in[25];
    const float* Wo2  = (const float*)d_in[26];
    const float* bo2  = (const float*)d_in[27];
    const int* ei     = (const int*)d_in[28];
    const int* et     = (const int*)d_in[29];
    const int* ntp    = (const int*)d_in[30];
    float* out = (float*)d_out;

    void* tmp;
    cudaGetSymbolAddress(&tmp, d_Wcat);  float* pWcat = (float*)tmp;
    cudaGetSymbolAddress(&tmp, d_XKMQ);  float* pXKMQ = (float*)tmp;
    cudaGetSymbolAddress(&tmp, d_aggr);  float* pAggr = (float*)tmp;
    cudaGetSymbolAddress(&tmp, d_Y1);    float* pY1   = (float*)tmp;
    cudaGetSymbolAddress(&tmp, d_bn3m);  float* pb3m  = (float*)tmp;
    cudaGetSymbolAddress(&tmp, d_bn3r);  float* pb3r  = (float*)tmp;

    k_zero<<<2048, 256>>>();
    k_nodehist<<<NN / 256, 256>>>(ntp);
    k_edgehist<<<EE / 256, 256>>>(ei, et, ntp);
    k_segsum<<<400, 256>>>(x);
    k_meanT<<<(NT1 * DD + 255) / 256, 256>>>();
    k_tables<<<NCOMBO + NTY, 256>>>(We1, be1);
    k_bnstat1<<<1, 256>>>();
    k_emb<<<NCOMBO + NTY, 256>>>(We2, be2, ge1, bte1);
    k_h2pre<<<NCOMBO, 256>>>(Wa1, ba1);
    k_bnstat2<<<1, 256>>>();
    k_Rtab<<<NCOMBO, 256>>>(Wa2, ba2, ga1, bta1);
    k_q<<<BB, 256>>>(sent, Watt);
    k_P<<<BB, 256>>>();
    k_graphsm<<<BB, 256>>>();
    k_upd<<<BB, 256>>>();
    k_ukum<<<BB + NTY, 256>>>(Wk, Wm);
    k_wcat<<<(DD * 600 + 255) / 256, 256>>>(Wk, Wm, Wq);
    {
        dim3 g((600 + BN_ - 1) / BN_, (NN + BM - 1) / BM);
        k_gemm<<<g, 256>>>(NN, 600, DD, x, DD, pWcat, 600, pXKMQ, 600,
                           nullptr, nullptr, nullptr, nullptr, nullptr);
    }
    k_D1<<<(TOTROWS + 7) / 8, 256>>>(ei, ntp, bq, bk);
    k_D2<<<(TOTROWS + 7) / 8, 256>>>(ei, ntp, bm);
    {
        dim3 g((DD + BN_ - 1) / BN_, (NN + BM - 1) / BM);
        k_gemm<<<g, 256>>>(NN, DD, DD, pAggr, DD, Wo1, DD, pY1, DD,
                           bo1, nullptr, nullptr, nullptr, nullptr);
    }
    k_colstat<<<NN / 256, 256>>>();
    k_stat3<<<1, 256>>>();
    {
        dim3 g((DD + BN_ - 1) / BN_, (NN + BM - 1) / BM);
        k_gemm<<<g, 256>>>(NN, DD, DD, pY1, DD, Wo2, DD, out, DD,
                           bo2, pb3m, pb3r, go1, bto1);
    }
}

// round 2
// speedup vs baseline: 1.1776x; 1.1776x over previous
#include <cuda_runtime.h>
#include <math.h>

#define DD 200
#define NTY 4
#define NET 38
#define NT1 39
#define BB 256
#define LL 1024
#define EE 262144
#define NN 51200
#define NCOMBO 608
#define TOTROWS (EE + NN)

// f32x2 packed-math helpers (FFMA2 — only reachable via PTX)
#define FMA2(d,a,b)  asm("fma.rn.f32x2 %0, %1, %2, %3;" : "=l"(d) : "l"(a), "l"(b), "l"(d))
#define PACK2(d,x,y) asm("mov.b64 %0, {%1, %2};" : "=l"(d) : "f"(x), "f"(y))
#define UNPACK2(x,y,d) asm("mov.b64 {%0, %1}, %2;" : "=f"(x), "=f"(y) : "l"(d))

// ------------------------- scratch (static device memory) -------------------------
__device__ float d_coeff[(size_t)NN * NT1];   // node-major: [n][etype]
__device__ float d_sums[NT1 * DD];
__device__ int   d_cntT[NT1];
__device__ int   d_cntE[NCOMBO];
__device__ int   d_cntN[NTY];
__device__ int   d_combo[EE];
__device__ int   d_cntSrc[NN];
__device__ float d_meanT[NT1 * DD];
__device__ float d_preE[NCOMBO * DD];
__device__ float d_preS[NTY * DD];
__device__ float d_embE[NCOMBO * DD];
__device__ float d_embS[NTY * DD];
__device__ float d_h2[NCOMBO * DD];
__device__ float d_Rtab[NCOMBO * DD];
__device__ float d_bn1m[DD], d_bn1r[DD], d_bn2m[DD], d_bn2r[DD], d_bn3m[DD], d_bn3r[DD];
__device__ float d_qv[BB * DD];
__device__ float d_P[BB * NCOMBO];
__device__ float d_Wt[BB * NCOMBO];
__device__ float d_upd[BB * DD];
__device__ float d_UK[BB * DD];
__device__ float d_UM[BB * DD];
__device__ float d_SK[NTY * DD];
__device__ float d_SM[NTY * DD];
__device__ float d_Wcat[DD * 640];            // padded to 640 cols
__device__ float d_Wo1P[DD * 256];
__device__ float d_Wo2P[DD * 256];
__device__ float d_XKMQ[(size_t)NN * 600];    // per-node [XK | XM | XQ]
__device__ float d_ex[(size_t)TOTROWS * 4];
__device__ float d_den[NN * 4];
__device__ float d_aggr[(size_t)NN * DD];
__device__ float d_Y1[(size_t)NN * DD];
__device__ float d_colsum[DD], d_colsum2[DD];

// ------------------------- zero init -------------------------
__global__ void k_zero() {
    long long i0 = (long long)blockIdx.x * blockDim.x + threadIdx.x;
    long long st = (long long)gridDim.x * blockDim.x;
    for (long long i = i0; i < (long long)NN * DD; i += st) d_aggr[i] = 0.f;
    for (long long i = i0; i < (long long)NT1 * NN; i += st) d_coeff[i] = 0.f;
    for (long long i = i0; i < (long long)NN * 4; i += st) d_den[i] = 0.f;
    for (long long i = i0; i < NT1 * DD; i += st) d_sums[i] = 0.f;
    for (long long i = i0; i < NCOMBO; i += st) d_cntE[i] = 0;
    for (long long i = i0; i < NT1; i += st) d_cntT[i] = 0;
    for (long long i = i0; i < NTY; i += st) d_cntN[i] = 0;
    for (long long i = i0; i < DD; i += st) { d_colsum[i] = 0.f; d_colsum2[i] = 0.f; }
}

// ------------------------- histograms -------------------------
__global__ void k_nodehist(const int* __restrict__ ntp) {
    int n = blockIdx.x * blockDim.x + threadIdx.x;
    if (n >= NN) return;
    d_cntSrc[n] = 1;                       // self loop
    atomicAdd(&d_cntN[ntp[n]], 1);
}

__global__ void k_edgehist(const int* __restrict__ ei, const int* __restrict__ et,
                           const int* __restrict__ ntp) {
    int e = blockIdx.x * blockDim.x + threadIdx.x;
    if (e >= EE) return;
    int s  = ei[e];
    int dd = ei[EE + e];
    int t  = et[e];
    atomicAdd(&d_coeff[(size_t)dd * NT1 + t],  1.f);
    atomicAdd(&d_coeff[(size_t)s  * NT1 + t], -1.f);
    atomicAdd(&d_cntT[t], 1);
    int c = (t << 4) | (ntp[s] << 2) | ntp[dd];
    d_combo[e] = c;
    atomicAdd(&d_cntE[c], 1);
    atomicAdd(&d_cntSrc[s], 1);
}

// ------------------------- segment sums: register-resident, sparse skip -------------------------
// 160 blocks x 128 threads; each block handles 320 nodes in batches of 32.
// Threads 0..99 own 2 columns each; 39 f32x2 accumulators in registers.
__global__ void k_segsum2(const float* __restrict__ x) {
    __shared__ float cf[32][40];
    int tid = threadIdx.x;
    unsigned long long acc[NT1];
#pragma unroll
    for (int t = 0; t < NT1; t++) acc[t] = 0ULL;
    int n0b = blockIdx.x * 320;
    for (int b = 0; b < 10; b++) {
        int n0 = n0b + b * 32;
        __syncthreads();
        for (int i = tid; i < 32 * NT1; i += 128)
            cf[i / NT1][i % NT1] = d_coeff[(size_t)(n0 + i / NT1) * NT1 + i % NT1];
        __syncthreads();
        if (tid < 100) {
            for (int nn = 0; nn < 32; nn++) {
                float2 xv = *(const float2*)&x[(size_t)(n0 + nn) * DD + tid * 2];
                unsigned long long xv2; PACK2(xv2, xv.x, xv.y);
#pragma unroll
                for (int t = 0; t < NT1; t++) {
                    float c = cf[nn][t];
                    if (c != 0.f) {                     // uniform branch (same for all threads)
                        unsigned long long c2; PACK2(c2, c, c);
                        FMA2(acc[t], c2, xv2);
                    }
                }
            }
        }
    }
    if (tid < 100) {
#pragma unroll
        for (int t = 0; t < NT1; t++) {
            float lo, hi; UNPACK2(lo, hi, acc[t]);
            if (lo != 0.f) atomicAdd(&d_sums[t * DD + tid * 2], lo);
            if (hi != 0.f) atomicAdd(&d_sums[t * DD + tid * 2 + 1], hi);
        }
    }
}

__global__ void k_meanT() {
    int i = blockIdx.x * blockDim.x + threadIdx.x;
    if (i >= NT1 * DD) return;
    int t = i / DD;
    float c = (float)d_cntT[t];
    if (c < 1.f) c = 1.f;
    d_meanT[i] = d_sums[i] / c;
}

// ------------------------- combo tables -------------------------
__global__ void k_tables(const float* __restrict__ We1, const float* __restrict__ be1) {
    int c = blockIdx.x, d = threadIdx.x;
    if (d >= DD) return;
    if (c < NCOMBO) {
        int t = c >> 4, a = (c >> 2) & 3, b = c & 3;
        d_preE[c * DD + d] = We1[t * DD + d] + We1[(NT1 + a) * DD + d]
                           + We1[(NT1 + NTY + b) * DD + d] + be1[d];
    } else {
        int t = c - NCOMBO;
        d_preS[t * DD + d] = We1[NET * DD + d] + We1[(NT1 + t) * DD + d]
                           + We1[(NT1 + NTY + t) * DD + d] + be1[d];
    }
}

__global__ void k_bnstat1() {
    int d = threadIdx.x;
    if (d >= DD) return;
    double s = 0.0, s2 = 0.0;
    for (int c = 0; c < NCOMBO; c++) {
        double w = (double)d_cntE[c], v = (double)d_preE[c * DD + d];
        s += w * v; s2 += w * v * v;
    }
    for (int t = 0; t < NTY; t++) {
        double w = (double)d_cntN[t], v = (double)d_preS[t * DD + d];
        s += w * v; s2 += w * v * v;
    }
    double m = s / (double)TOTROWS;
    double var = s2 / (double)TOTROWS - m * m;
    d_bn1m[d] = (float)m;
    d_bn1r[d] = rsqrtf((float)var + 1e-5f);
}

__global__ void k_emb(const float* __restrict__ We2, const float* __restrict__ be2,
                      const float* __restrict__ g, const float* __restrict__ bt) {
    int c = blockIdx.x, d = threadIdx.x;
    __shared__ float a[DD];
    const float* srow = (c < NCOMBO) ? &d_preE[c * DD] : &d_preS[(c - NCOMBO) * DD];
    if (d < DD) {
        float v = (srow[d] - d_bn1m[d]) * d_bn1r[d] * g[d] + bt[d];
        a[d] = fmaxf(v, 0.f);
    }
    __syncthreads();
    if (d < DD) {
        float acc = 0.f;
        for (int k = 0; k < DD; k++) acc += a[k] * We2[k * DD + d];
        float* dst = (c < NCOMBO) ? &d_embE[c * DD] : &d_embS[(c - NCOMBO) * DD];
        dst[d] = acc + be2[d];
    }
}

__global__ void k_h2pre(const float* __restrict__ Wa1, const float* __restrict__ ba1) {
    int c = blockIdx.x, d = threadIdx.x;
    __shared__ float e[DD], mt[DD];
    int t = c >> 4;
    if (d < DD) { e[d] = d_embE[c * DD + d]; mt[d] = d_meanT[t * DD + d]; }
    __syncthreads();
    if (d < DD) {
        float acc = ba1[d];
        for (int k = 0; k < DD; k++) acc += e[k] * Wa1[k * DD + d];
        for (int k = 0; k < DD; k++) acc += mt[k] * Wa1[(DD + k) * DD + d];
        d_h2[c * DD + d] = acc;
    }
}

__global__ void k_bnstat2() {
    int d = threadIdx.x;
    if (d >= DD) return;
    double s = 0.0, s2 = 0.0;
    for (int c = 0; c < NCOMBO; c++) {
        double w = (double)d_cntE[c], v = (double)d_h2[c * DD + d];
        s += w * v; s2 += w * v * v;
    }
    double m = s / (double)EE;
    double var = s2 / (double)EE - m * m;
    d_bn2m[d] = (float)m;
    d_bn2r[d] = rsqrtf((float)var + 1e-5f);
}

__global__ void k_Rtab(const float* __restrict__ Wa2, const float* __restrict__ ba2,
                       const float* __restrict__ g, const float* __restrict__ bt) {
    int c = blockIdx.x, d = threadIdx.x;
    __shared__ float a[DD];
    if (d < DD) {
        float v = (d_h2[c * DD + d] - d_bn2m[d]) * d_bn2r[d] * g[d] + bt[d];
        a[d] = fmaxf(v, 0.f);
    }
    __syncthreads();
    if (d < DD) {
        float acc = 0.f;
        for (int k = 0; k < DD; k++) acc += a[k] * Wa2[k * DD + d];
        d_Rtab[c * DD + d] = acc + ba2[d];
    }
}

// ------------------------- graph attention -------------------------
__global__ void k_q(const float* __restrict__ sent, const float* __restrict__ Watt) {
    int b = blockIdx.x, d = threadIdx.x;
    __shared__ float s[DD];
    if (d < DD) s[d] = sent[b * DD + d];
    __syncthreads();
    if (d < DD) {
        float acc = 0.f;
        for (int k = 0; k < DD; k++) acc += s[k] * Watt[k * DD + d];
        d_qv[b * DD + d] = acc;
    }
}

__global__ void k_P() {
    int b = blockIdx.x, tid = threadIdx.x, lane = tid & 31, w = tid >> 5;
    __shared__ float q[DD];
    for (int i = tid; i < DD; i += blockDim.x)
        q[i] = d_qv[b * DD + i] * 0.07071067811865475f;  // 1/sqrt(200)
    __syncthreads();
    for (int c = w; c < NCOMBO; c += 8) {
        float p = 0.f;
        for (int k = lane; k < DD; k += 32) p += q[k] * d_Rtab[c * DD + k];
        for (int o = 16; o > 0; o >>= 1) p += __shfl_down_sync(0xffffffffu, p, o);
        if (lane == 0) d_P[b * NCOMBO + c] = p;
    }
}

__global__ void k_graphsm() {
    int b = blockIdx.x, tid = threadIdx.x;
    __shared__ float Pb[NCOMBO];
    __shared__ float Wacc[NCOMBO];
    __shared__ float red[256];
    for (int i = tid; i < NCOMBO; i += 256) { Pb[i] = d_P[b * NCOMBO + i]; Wacc[i] = 0.f; }
    __syncthreads();
    int cid[4]; float sc[4]; float lmax = -1e30f;
#pragma unroll
    for (int j = 0; j < 4; j++) {
        int e = b * LL + tid + j * 256;
        cid[j] = d_combo[e];
        sc[j] = Pb[cid[j]];
        lmax = fmaxf(lmax, sc[j]);
    }
    red[tid] = lmax; __syncthreads();
    for (int s = 128; s > 0; s >>= 1) { if (tid < s) red[tid] = fmaxf(red[tid], red[tid + s]); __syncthreads(); }
    float bmax = red[0]; __syncthreads();
    float lsum = 0.f;
#pragma unroll
    for (int j = 0; j < 4; j++) { sc[j] = expf(sc[j] - bmax); lsum += sc[j]; }
    red[tid] = lsum; __syncthreads();
    for (int s = 128; s > 0; s >>= 1) { if (tid < s) red[tid] += red[tid + s]; __syncthreads(); }
    float inv = 1.f / red[0]; __syncthreads();
#pragma unroll
    for (int j = 0; j < 4; j++) atomicAdd(&Wacc[cid[j]], sc[j] * inv);
    __syncthreads();
    for (int i = tid; i < NCOMBO; i += 256) d_Wt[b * NCOMBO + i] = Wacc[i];
}

__global__ void k_upd() {
    int b = blockIdx.x, d = threadIdx.x;
    __shared__ float w[NCOMBO];
    for (int i = d; i < NCOMBO; i += blockDim.x) w[i] = d_Wt[b * NCOMBO + i];
    __syncthreads();
    if (d < DD) {
        float acc = 0.f;
        for (int c = 0; c < NCOMBO; c++) acc += w[c] * d_Rtab[c * DD + d];
        d_upd[b * DD + d] = acc;
    }
}

__global__ void k_ukum(const float* __restrict__ Wk, const float* __restrict__ Wm) {
    int id = blockIdx.x, d = threadIdx.x;
    __shared__ float s[DD];
    const float* srow; float *ok, *om;
    if (id < BB) { srow = &d_upd[id * DD]; ok = &d_UK[id * DD]; om = &d_UM[id * DD]; }
    else { int t = id - BB; srow = &d_embS[t * DD]; ok = &d_SK[t * DD]; om = &d_SM[t * DD]; }
    if (d < DD) s[d] = srow[d];
    __syncthreads();
    if (d < DD) {
        float ak = 0.f, am = 0.f;
        for (int k = 0; k < DD; k++) {
            float sv = s[k];
            ak += sv * Wk[(DD + k) * DD + d];
            am += sv * Wm[(DD + k) * DD + d];
        }
        ok[d] = ak; om[d] = am;
    }
}

// ------------------------- weight packing -------------------------
__global__ void k_wcat(const float* __restrict__ Wk, const float* __restrict__ Wm,
                       const float* __restrict__ Wq) {
    int i = blockIdx.x * blockDim.x + threadIdx.x;
    if (i >= DD * 640) return;
    int k = i / 640, c = i % 640;
    float v = (c < DD) ? Wk[k * DD + c]
            : (c < 2 * DD) ? Wm[k * DD + (c - DD)]
            : (c < 3 * DD) ? Wq[k * DD + (c - 2 * DD)] : 0.f;
    d_Wcat[i] = v;
}

__global__ void k_wpad(const float* __restrict__ W, float* __restrict__ P) {
    int i = blockIdx.x * blockDim.x + threadIdx.x;
    if (i >= DD * 256) return;
    int k = i >> 8, c = i & 255;
    P[i] = (c < DD) ? W[k * DD + c] : 0.f;
}

// ------------------------- f32x2 packed GEMM: 128x128 tile, 8x8/thread -------------------------
// C[M,Nreal] = op(A[M,K]) @ B[K,ldb] (+bias); op = optional BN+relu per A element.
// Requires: M%128==0, K%8==0, lda%4==0, B padded so col0+127 < ldb.
__global__ __launch_bounds__(256, 2) void k_gemm2(
    int M, int Nreal, int K,
    const float* __restrict__ A, int lda,
    const float* __restrict__ B, int ldb,
    float* __restrict__ C, int ldc,
    const float* __restrict__ bias,
    const float* __restrict__ bnm, const float* __restrict__ bnr,
    const float* __restrict__ bng, const float* __restrict__ bnb) {
    __shared__ float As[8][128];
    __shared__ float Bs[8][128];
    int tid = threadIdx.x;
    int row0 = blockIdx.y * 128, col0 = blockIdx.x * 128;
    int ty = tid >> 4, tx = tid & 15;
    unsigned long long acc[8][4];
#pragma unroll
    for (int i = 0; i < 8; i++)
#pragma unroll
        for (int j = 0; j < 4; j++) acc[i][j] = 0ULL;
    int rowA = row0 + (tid >> 1);
    int kA = (tid & 1) * 4;
    int rowB = tid >> 5;
    int colB = (tid & 31) * 4;
    for (int k0 = 0; k0 < K; k0 += 8) {
        float4 av = *(const float4*)&A[(size_t)rowA * lda + k0 + kA];
        if (bnm) {
            int g = k0 + kA;
            av.x = fmaxf((av.x - bnm[g])     * bnr[g]     * bng[g]     + bnb[g],     0.f);
            av.y = fmaxf((av.y - bnm[g + 1]) * bnr[g + 1] * bng[g + 1] + bnb[g + 1], 0.f);
            av.z = fmaxf((av.z - bnm[g + 2]) * bnr[g + 2] * bng[g + 2] + bnb[g + 2], 0.f);
            av.w = fmaxf((av.w - bnm[g + 3]) * bnr[g + 3] * bng[g + 3] + bnb[g + 3], 0.f);
        }
        int m = tid >> 1;
        As[kA + 0][m] = av.x; As[kA + 1][m] = av.y;
        As[kA + 2][m] = av.z; As[kA + 3][m] = av.w;
        *(float4*)&Bs[rowB][colB] = *(const float4*)&B[(size_t)(k0 + rowB) * ldb + col0 + colB];
        __syncthreads();
#pragma unroll
        for (int kk = 0; kk < 8; kk++) {
            float4 a0 = *(const float4*)&As[kk][ty * 8];
            float4 a1 = *(const float4*)&As[kk][ty * 8 + 4];
            ulonglong2 b01 = *(const ulonglong2*)&Bs[kk][tx * 8];
            ulonglong2 b23 = *(const ulonglong2*)&Bs[kk][tx * 8 + 4];
            unsigned long long bb[4] = { b01.x, b01.y, b23.x, b23.y };
            unsigned long long a2[8];
            PACK2(a2[0], a0.x, a0.x); PACK2(a2[1], a0.y, a0.y);
            PACK2(a2[2], a0.z, a0.z); PACK2(a2[3], a0.w, a0.w);
            PACK2(a2[4], a1.x, a1.x); PACK2(a2[5], a1.y, a1.y);
            PACK2(a2[6], a1.z, a1.z); PACK2(a2[7], a1.w, a1.w);
#pragma unroll
            for (int i = 0; i < 8; i++) {
                FMA2(acc[i][0], a2[i], bb[0]);
                FMA2(acc[i][1], a2[i], bb[1]);
                FMA2(acc[i][2], a2[i], bb[2]);
                FMA2(acc[i][3], a2[i], bb[3]);
            }
        }
        __syncthreads();
    }
#pragma unroll
    for (int i = 0; i < 8; i++) {
        int r = row0 + ty * 8 + i;
        float* crow = &C[(size_t)r * ldc];
#pragma unroll
        for (int j = 0; j < 4; j++) {
            float lo, hi; UNPACK2(lo, hi, acc[i][j]);
            int c0 = col0 + tx * 8 + j * 2;
            if (c0 < Nreal)     crow[c0]     = lo + (bias ? bias[c0]     : 0.f);
            if (c0 + 1 < Nreal) crow[c0 + 1] = hi + (bias ? bias[c0 + 1] : 0.f);
        }
    }
}

// ------------------------- edge attention passes -------------------------
__global__ void k_D1(const int* __restrict__ ei, const int* __restrict__ ntp,
                     const float* __restrict__ bq, const float* __restrict__ bk) {
    int warp = (blockIdx.x * blockDim.x + threadIdx.x) >> 5;
    int lane = threadIdx.x & 31;
    if (warp >= TOTROWS) return;
    int i = warp;
    int s, dd; const float* kadd;
    if (i < EE) { s = ei[i]; dd = ei[EE + i]; kadd = &d_UK[(i >> 10) * DD]; }
    else { int n = i - EE; s = n; dd = n; kadd = &d_SK[ntp[n] * DD]; }
    const float* qrow = &d_XKMQ[(size_t)s * 600 + 400];
    const float* krow = &d_XKMQ[(size_t)dd * 600];
    const float invs = 0.1414213562373095f;  // 1/sqrt(50)
#pragma unroll
    for (int h = 0; h < 4; h++) {
        float p = 0.f;
        if (lane < 25) {
            int d0 = h * 50 + lane * 2;
            float2 q2 = *(const float2*)(qrow + d0);
            float2 k2 = *(const float2*)(krow + d0);
            float2 a2 = *(const float2*)(kadd + d0);
            float2 bq2 = *(const float2*)(bq + d0);
            float2 bk2 = *(const float2*)(bk + d0);
            float qa = (q2.x + bq2.x) * invs, qb = (q2.y + bq2.y) * invs;
            float ka = k2.x + a2.x + bk2.x, kb = k2.y + a2.y + bk2.y;
            p = qa * ka + qb * kb;
        }
        for (int o = 16; o > 0; o >>= 1) p += __shfl_down_sync(0xffffffffu, p, o);
        if (lane == 0) {
            float exv = expf(p);   // shift-invariant softmax; |p| << 1 so exp is safe
            d_ex[(size_t)i * 4 + h] = exv;
            atomicAdd(&d_den[s * 4 + h], exv);
        }
    }
}

__global__ void k_D2(const int* __restrict__ ei, const int* __restrict__ ntp,
                     const float* __restrict__ bm) {
    int warp = (blockIdx.x * blockDim.x + threadIdx.x) >> 5;
    int lane = threadIdx.x & 31;
    if (warp >= TOTROWS) return;
    int i = warp;
    int s, j, dn; const float* madd;
    if (i < EE) { s = ei[i]; j = s; dn = ei[EE + i]; madd = &d_UM[(i >> 10) * DD]; }
    else { int n = i - EE; s = n; j = n; dn = n; madd = &d_SM[ntp[n] * DD]; }
    float av = 0.f;
    if (lane < 4)
        av = d_ex[(size_t)i * 4 + lane] / d_den[s * 4 + lane] * (float)d_cntSrc[s];
    float a0 = __shfl_sync(0xffffffffu, av, 0);
    float a1 = __shfl_sync(0xffffffffu, av, 1);
    float a2v = __shfl_sync(0xffffffffu, av, 2);
    float a3 = __shfl_sync(0xffffffffu, av, 3);
    const float* mrow = &d_XKMQ[(size_t)j * 600 + 200];
    float* arow = &d_aggr[(size_t)dn * DD];
    for (int u = lane; u < 50; u += 32) {
        int d0 = u * 4;
        float4 xm = *(const float4*)(mrow + d0);
        float4 ad = *(const float4*)(madd + d0);
        float4 bb = *(const float4*)(bm + d0);
        float v0 = xm.x + ad.x + bb.x, v1 = xm.y + ad.y + bb.y;
        float v2 = xm.z + ad.z + bb.z, v3 = xm.w + ad.w + bb.w;
        float al0 = (d0 + 0) < 50 ? a0 : (d0 + 0) < 100 ? a1 : (d0 + 0) < 150 ? a2v : a3;
        float al1 = (d0 + 1) < 50 ? a0 : (d0 + 1) < 100 ? a1 : (d0 + 1) < 150 ? a2v : a3;
        float al2 = (d0 + 2) < 50 ? a0 : (d0 + 2) < 100 ? a1 : (d0 + 2) < 150 ? a2v : a3;
        float al3 = (d0 + 3) < 50 ? a0 : (d0 + 3) < 100 ? a1 : (d0 + 3) < 150 ? a2v : a3;
        v0 *= al0; v1 *= al1; v2 *= al2; v3 *= al3;
        asm volatile("red.global.add.v4.f32 [%0], {%1,%2,%3,%4};"
                     :: "l"(arow + d0), "f"(v0), "f"(v1), "f"(v2), "f"(v3) : "memory");
    }
}

// ------------------------- output BN stats -------------------------
__global__ void k_colstat() {
    int d = threadIdx.x;
    if (d >= DD) return;
    int r0 = blockIdx.x * 256;
    float s = 0.f, s2 = 0.f;
    for (int r = r0; r < r0 + 256; r++) {
        float v = d_Y1[(size_t)r * DD + d];
        s += v; s2 += v * v;
    }
    atomicAdd(&d_colsum[d], s);
    atomicAdd(&d_colsum2[d], s2);
}

__global__ void k_stat3() {
    int d = threadIdx.x;
    if (d >= DD) return;
    float m = d_colsum[d] / (float)NN;
    float var = d_colsum2[d] / (float)NN - m * m;
    d_bn3m[d] = m;
    d_bn3r[d] = rsqrtf(var + 1e-5f);
}

// ------------------------- launch -------------------------
extern "C" void kernel_launch(void* const* d_in, const int* in_sizes, int n_in,
                              void* d_out, int out_size) {
    const float* x    = (const float*)d_in[0];
    const float* sent = (const float*)d_in[2];
    const float* We1  = (const float*)d_in[3];
    const float* be1  = (const float*)d_in[4];
    const float* ge1  = (const float*)d_in[5];
    const float* bte1 = (const float*)d_in[6];
    const float* We2  = (const float*)d_in[7];
    const float* be2  = (const float*)d_in[8];
    const float* Wa1  = (const float*)d_in[9];
    const float* ba1  = (const float*)d_in[10];
    const float* ga1  = (const float*)d_in[11];
    const float* bta1 = (const float*)d_in[12];
    const float* Wa2  = (const float*)d_in[13];
    const float* ba2  = (const float*)d_in[14];
    const float* Watt = (const float*)d_in[15];
    const float* Wk   = (const float*)d_in[16];
    const float* bk   = (const float*)d_in[17];
    const float* Wm   = (const float*)d_in[18];
    const float* bm   = (const float*)d_in[19];
    const float* Wq   = (const float*)d_in[20];
    const float* bq   = (const float*)d_in[21];
    const float* Wo1  = (const float*)d_in[22];
    const float* bo1  = (const float*)d_in[23];
    const float* go1  = (const float*)d_in[24];
    const float* bto1 = (const float*)d_in[25];
    const float* Wo2  = (const float*)d_in[26];
    const float* bo2  = (const float*)d_in[27];
    const int* ei     = (const int*)d_in[28];
    const int* et     = (const int*)d_in[29];
    const int* ntp    = (const int*)d_in[30];
    float* out = (float*)d_out;

    void* tmp;
    cudaGetSymbolAddress(&tmp, d_Wcat);  float* pWcat = (float*)tmp;
    cudaGetSymbolAddress(&tmp, d_Wo1P);  float* pWo1P = (float*)tmp;
    cudaGetSymbolAddress(&tmp, d_Wo2P);  float* pWo2P = (float*)tmp;
    cudaGetSymbolAddress(&tmp, d_XKMQ);  float* pXKMQ = (float*)tmp;
    cudaGetSymbolAddress(&tmp, d_aggr);  float* pAggr = (float*)tmp;
    cudaGetSymbolAddress(&tmp, d_Y1);    float* pY1   = (float*)tmp;
    cudaGetSymbolAddress(&tmp, d_bn3m);  float* pb3m  = (float*)tmp;
    cudaGetSymbolAddress(&tmp, d_bn3r);  float* pb3r  = (float*)tmp;

    k_zero<<<2048, 256>>>();
    k_nodehist<<<NN / 256, 256>>>(ntp);
    k_edgehist<<<EE / 256, 256>>>(ei, et, ntp);
    k_segsum2<<<160, 128>>>(x);
    k_meanT<<<(NT1 * DD + 255) / 256, 256>>>();
    k_tables<<<NCOMBO + NTY, 256>>>(We1, be1);
    k_bnstat1<<<1, 256>>>();
    k_emb<<<NCOMBO + NTY, 256>>>(We2, be2, ge1, bte1);
    k_h2pre<<<NCOMBO, 256>>>(Wa1, ba1);
    k_bnstat2<<<1, 256>>>();
    k_Rtab<<<NCOMBO, 256>>>(Wa2, ba2, ga1, bta1);
    k_q<<<BB, 256>>>(sent, Watt);
    k_P<<<BB, 256>>>();
    k_graphsm<<<BB, 256>>>();
    k_upd<<<BB, 256>>>();
    k_ukum<<<BB + NTY, 256>>>(Wk, Wm);
    k_wcat<<<(DD * 640 + 255) / 256, 256>>>(Wk, Wm, Wq);
    k_wpad<<<(DD * 256 + 255) / 256, 256>>>(Wo1, pWo1P);
    k_wpad<<<(DD * 256 + 255) / 256, 256>>>(Wo2, pWo2P);
    {   // XKMQ = x @ [Wk1|Wm1|Wq]  (51200 x 600 x 200)
        dim3 g(5, NN / 128);
        k_gemm2<<<g, 256>>>(NN, 600, DD, x, DD, pWcat, 640, pXKMQ, 600,
                            nullptr, nullptr, nullptr, nullptr, nullptr);
    }
    k_D1<<<(TOTROWS + 7) / 8, 256>>>(ei, ntp, bq, bk);
    k_D2<<<(TOTROWS + 7) / 8, 256>>>(ei, ntp, bm);
    {   // Y1 = aggr @ Wo1 + bo1
        dim3 g(2, NN / 128);
        k_gemm2<<<g, 256>>>(NN, DD, DD, pAggr, DD, pWo1P, 256, pY1, DD,
                            bo1, nullptr, nullptr, nullptr, nullptr);
    }
    k_colstat<<<NN / 256, 256>>>();
    k_stat3<<<1, 256>>>();
    {   // out = relu(bn(Y1)) @ Wo2 + bo2
        dim3 g(2, NN / 128);
        k_gemm2<<<g, 256>>>(NN, DD, DD, pY1, DD, pWo2P, 256, out, DD,
                            bo2, pb3m, pb3r, go1, bto1);
    }
}

// round 3
// speedup vs baseline: 1.4677x; 1.2463x over previous
#include <cuda_runtime.h>
#include <math.h>

#define DD 200
#define NTY 4
#define NET 38
#define NT1 39
#define BB 256
#define LL 1024
#define EE 262144
#define NN 51200
#define NCOMBO 608
#define TOTROWS (EE + NN)

// f32x2 packed-math helpers (FFMA2 — only reachable via PTX)
#define FMA2(d,a,b)  asm("fma.rn.f32x2 %0, %1, %2, %3;" : "=l"(d) : "l"(a), "l"(b), "l"(d))
#define PACK2(d,x,y) asm("mov.b64 %0, {%1, %2};" : "=l"(d) : "f"(x), "f"(y))
#define UNPACK2(x,y,d) asm("mov.b64 {%0, %1}, %2;" : "=f"(x), "=f"(y) : "l"(d))

// ------------------------- scratch (static device memory) -------------------------
__device__ float d_coeff[(size_t)NN * NT1];   // node-major: [n][etype]
__device__ float d_sums[NT1 * DD];
__device__ int   d_cntT[NT1];
__device__ int   d_cntE[NCOMBO];
__device__ int   d_cntN[NTY];
__device__ int   d_combo[EE];
__device__ int   d_cntSrc[NN];
__device__ int   d_dstCnt[NN];
__device__ int   d_dstOff[NN + 1];
__device__ int   d_cursor[NN];
__device__ int   d_csr[TOTROWS];
__device__ float d_meanT[NT1 * DD];
__device__ float d_preE[NCOMBO * DD];
__device__ float d_preS[NTY * DD];
__device__ float d_embE[NCOMBO * DD];
__device__ float d_embS[NTY * DD];
__device__ float d_h2[NCOMBO * DD];
__device__ float d_Rtab[NCOMBO * DD];
__device__ float d_bn1m[DD], d_bn1r[DD], d_bn2m[DD], d_bn2r[DD], d_bn3m[DD], d_bn3r[DD];
__device__ float d_qv[BB * DD];
__device__ float d_P[BB * NCOMBO];
__device__ float d_Wt[BB * NCOMBO];
__device__ float d_upd[BB * DD];
__device__ float d_UKall[(BB + NTY) * DD];    // rows 0..255 = per-graph, 256..259 = per-ntype
__device__ float d_UMall[(BB + NTY) * DD];
__device__ float d_Wcat[DD * 640];            // padded to 640 cols
__device__ float d_Wo1P[DD * 256];
__device__ float d_Wo2P[DD * 256];
__device__ float d_XKMQ[(size_t)NN * 600];    // per-node [XK | XM | XQ]
__device__ float d_ex[(size_t)TOTROWS * 4];
__device__ float d_den[NN * 4];
__device__ float d_aggr[(size_t)NN * DD];
__device__ float d_Y1[(size_t)NN * DD];
__device__ float d_colsum[DD], d_colsum2[DD];

// ------------------------- zero init -------------------------
__global__ void k_zero() {
    long long i0 = (long long)blockIdx.x * blockDim.x + threadIdx.x;
    long long st = (long long)gridDim.x * blockDim.x;
    for (long long i = i0; i < (long long)NT1 * NN; i += st) d_coeff[i] = 0.f;
    for (long long i = i0; i < (long long)NN * 4; i += st) d_den[i] = 0.f;
    for (long long i = i0; i < NT1 * DD; i += st) d_sums[i] = 0.f;
    for (long long i = i0; i < NCOMBO; i += st) d_cntE[i] = 0;
    for (long long i = i0; i < NT1; i += st) d_cntT[i] = 0;
    for (long long i = i0; i < NTY; i += st) d_cntN[i] = 0;
    for (long long i = i0; i < DD; i += st) { d_colsum[i] = 0.f; d_colsum2[i] = 0.f; }
}

// ------------------------- histograms -------------------------
__global__ void k_nodehist(const int* __restrict__ ntp) {
    int n = blockIdx.x * blockDim.x + threadIdx.x;
    if (n >= NN) return;
    d_cntSrc[n] = 1;                       // self loop (as src)
    d_dstCnt[n] = 1;                       // self loop (as dst)
    atomicAdd(&d_cntN[ntp[n]], 1);
}

__global__ void k_edgehist(const int* __restrict__ ei, const int* __restrict__ et,
                           const int* __restrict__ ntp) {
    int e = blockIdx.x * blockDim.x + threadIdx.x;
    if (e >= EE) return;
    int s  = ei[e];
    int dd = ei[EE + e];
    int t  = et[e];
    atomicAdd(&d_coeff[(size_t)dd * NT1 + t],  1.f);
    atomicAdd(&d_coeff[(size_t)s  * NT1 + t], -1.f);
    atomicAdd(&d_cntT[t], 1);
    int c = (t << 4) | (ntp[s] << 2) | ntp[dd];
    d_combo[e] = c;
    atomicAdd(&d_cntE[c], 1);
    atomicAdd(&d_cntSrc[s], 1);
    atomicAdd(&d_dstCnt[dd], 1);
}

// ------------------------- dst-CSR build -------------------------
__global__ void k_scan() {               // 1 block, 1024 threads; NN = 1024*50
    __shared__ int part[1024];
    int tid = threadIdx.x;
    int base = tid * 50;
    int s = 0;
#pragma unroll 5
    for (int i = 0; i < 50; i++) s += d_dstCnt[base + i];
    part[tid] = s;
    __syncthreads();
    for (int off = 1; off < 1024; off <<= 1) {
        int v = (tid >= off) ? part[tid - off] : 0;
        __syncthreads();
        part[tid] += v;
        __syncthreads();
    }
    int run = part[tid] - s;             // exclusive prefix for this chunk
    for (int i = 0; i < 50; i++) {
        int c = d_dstCnt[base + i];
        d_dstOff[base + i] = run;
        d_cursor[base + i] = run;
        run += c;
    }
    if (tid == 1023) d_dstOff[NN] = run;
}

__global__ void k_csrfill(const int* __restrict__ ei) {
    int i = blockIdx.x * blockDim.x + threadIdx.x;
    if (i >= TOTROWS) return;
    int dst = (i < EE) ? ei[EE + i] : (i - EE);
    int pos = atomicAdd(&d_cursor[dst], 1);
    d_csr[pos] = i;
}

// ------------------------- segment sums: dense f32x2, smem-duplicated coeffs -------------------------
// grid 400 x 128 threads; 128 nodes/block; threads 0..99 own 2 columns each.
__global__ __launch_bounds__(128) void k_segsum3(const float* __restrict__ x) {
    __shared__ unsigned long long cf2[128][NT1];   // 39.9 KB, coeff duplicated lo/hi
    int tid = threadIdx.x;
    int n0 = blockIdx.x * 128;
    for (int i = tid; i < 128 * NT1; i += 128) {
        float c = d_coeff[(size_t)(n0 + i / NT1) * NT1 + (i % NT1)];
        unsigned long long c2; PACK2(c2, c, c);
        cf2[i / NT1][i % NT1] = c2;
    }
    __syncthreads();
    if (tid < 100) {
        unsigned long long acc[NT1];
#pragma unroll
        for (int t = 0; t < NT1; t++) acc[t] = 0ULL;
        for (int nn = 0; nn < 128; nn++) {
            float2 xv = *(const float2*)&x[(size_t)(n0 + nn) * DD + tid * 2];
            unsigned long long xv2; PACK2(xv2, xv.x, xv.y);
#pragma unroll
            for (int t = 0; t < NT1; t++)
                FMA2(acc[t], cf2[nn][t], xv2);
        }
#pragma unroll
        for (int t = 0; t < NT1; t++) {
            float lo, hi; UNPACK2(lo, hi, acc[t]);
            if (lo != 0.f) atomicAdd(&d_sums[t * DD + tid * 2], lo);
            if (hi != 0.f) atomicAdd(&d_sums[t * DD + tid * 2 + 1], hi);
        }
    }
}

__global__ void k_meanT() {
    int i = blockIdx.x * blockDim.x + threadIdx.x;
    if (i >= NT1 * DD) return;
    int t = i / DD;
    float c = (float)d_cntT[t];
    if (c < 1.f) c = 1.f;
    d_meanT[i] = d_sums[i] / c;
}

// ------------------------- combo tables -------------------------
__global__ void k_tables(const float* __restrict__ We1, const float* __restrict__ be1) {
    int c = blockIdx.x, d = threadIdx.x;
    if (d >= DD) return;
    if (c < NCOMBO) {
        int t = c >> 4, a = (c >> 2) & 3, b = c & 3;
        d_preE[c * DD + d] = We1[t * DD + d] + We1[(NT1 + a) * DD + d]
                           + We1[(NT1 + NTY + b) * DD + d] + be1[d];
    } else {
        int t = c - NCOMBO;
        d_preS[t * DD + d] = We1[NET * DD + d] + We1[(NT1 + t) * DD + d]
                           + We1[(NT1 + NTY + t) * DD + d] + be1[d];
    }
}

// parallel BN stats: one block per output column d
__global__ void k_bnstat1p() {
    int d = blockIdx.x, tid = threadIdx.x;
    __shared__ double rs[128], rs2[128];
    double s = 0.0, s2 = 0.0;
    for (int c = tid; c < NCOMBO; c += 128) {
        double w = (double)d_cntE[c], v = (double)d_preE[c * DD + d];
        s += w * v; s2 += w * v * v;
    }
    if (tid < NTY) {
        double w = (double)d_cntN[tid], v = (double)d_preS[tid * DD + d];
        s += w * v; s2 += w * v * v;
    }
    rs[tid] = s; rs2[tid] = s2;
    __syncthreads();
    for (int o = 64; o > 0; o >>= 1) {
        if (tid < o) { rs[tid] += rs[tid + o]; rs2[tid] += rs2[tid + o]; }
        __syncthreads();
    }
    if (tid == 0) {
        double m = rs[0] / (double)TOTROWS;
        double var = rs2[0] / (double)TOTROWS - m * m;
        d_bn1m[d] = (float)m;
        d_bn1r[d] = rsqrtf((float)var + 1e-5f);
    }
}

__global__ void k_emb(const float* __restrict__ We2, const float* __restrict__ be2,
                      const float* __restrict__ g, const float* __restrict__ bt) {
    int c = blockIdx.x, d = threadIdx.x;
    __shared__ float a[DD];
    const float* srow = (c < NCOMBO) ? &d_preE[c * DD] : &d_preS[(c - NCOMBO) * DD];
    if (d < DD) {
        float v = (srow[d] - d_bn1m[d]) * d_bn1r[d] * g[d] + bt[d];
        a[d] = fmaxf(v, 0.f);
    }
    __syncthreads();
    if (d < DD) {
        float acc = 0.f;
        for (int k = 0; k < DD; k++) acc += a[k] * We2[k * DD + d];
        float* dst = (c < NCOMBO) ? &d_embE[c * DD] : &d_embS[(c - NCOMBO) * DD];
        dst[d] = acc + be2[d];
    }
}

__global__ void k_h2pre(const float* __restrict__ Wa1, const float* __restrict__ ba1) {
    int c = blockIdx.x, d = threadIdx.x;
    __shared__ float e[DD], mt[DD];
    int t = c >> 4;
    if (d < DD) { e[d] = d_embE[c * DD + d]; mt[d] = d_meanT[t * DD + d]; }
    __syncthreads();
    if (d < DD) {
        float acc = ba1[d];
        for (int k = 0; k < DD; k++) acc += e[k] * Wa1[k * DD + d];
        for (int k = 0; k < DD; k++) acc += mt[k] * Wa1[(DD + k) * DD + d];
        d_h2[c * DD + d] = acc;
    }
}

__global__ void k_bnstat2p() {
    int d = blockIdx.x, tid = threadIdx.x;
    __shared__ double rs[128], rs2[128];
    double s = 0.0, s2 = 0.0;
    for (int c = tid; c < NCOMBO; c += 128) {
        double w = (double)d_cntE[c], v = (double)d_h2[c * DD + d];
        s += w * v; s2 += w * v * v;
    }
    rs[tid] = s; rs2[tid] = s2;
    __syncthreads();
    for (int o = 64; o > 0; o >>= 1) {
        if (tid < o) { rs[tid] += rs[tid + o]; rs2[tid] += rs2[tid + o]; }
        __syncthreads();
    }
    if (tid == 0) {
        double m = rs[0] / (double)EE;
        double var = rs2[0] / (double)EE - m * m;
        d_bn2m[d] = (float)m;
        d_bn2r[d] = rsqrtf((float)var + 1e-5f);
    }
}

__global__ void k_Rtab(const float* __restrict__ Wa2, const float* __restrict__ ba2,
                       const float* __restrict__ g, const float* __restrict__ bt) {
    int c = blockIdx.x, d = threadIdx.x;
    __shared__ float a[DD];
    if (d < DD) {
        float v = (d_h2[c * DD + d] - d_bn2m[d]) * d_bn2r[d] * g[d] + bt[d];
        a[d] = fmaxf(v, 0.f);
    }
    __syncthreads();
    if (d < DD) {
        float acc = 0.f;
        for (int k = 0; k < DD; k++) acc += a[k] * Wa2[k * DD + d];
        d_Rtab[c * DD + d] = acc + ba2[d];
    }
}

// ------------------------- graph attention -------------------------
__global__ void k_q(const float* __restrict__ sent, const float* __restrict__ Watt) {
    int b = blockIdx.x, d = threadIdx.x;
    __shared__ float s[DD];
    if (d < DD) s[d] = sent[b * DD + d];
    __syncthreads();
    if (d < DD) {
        float acc = 0.f;
        for (int k = 0; k < DD; k++) acc += s[k] * Watt[k * DD + d];
        d_qv[b * DD + d] = acc;
    }
}

__global__ void k_P() {
    int b = blockIdx.x, tid = threadIdx.x, lane = tid & 31, w = tid >> 5;
    __shared__ float q[DD];
    for (int i = tid; i < DD; i += blockDim.x)
        q[i] = d_qv[b * DD + i] * 0.07071067811865475f;  // 1/sqrt(200)
    __syncthreads();
    for (int c = w; c < NCOMBO; c += 8) {
        float p = 0.f;
        for (int k = lane; k < DD; k += 32) p += q[k] * d_Rtab[c * DD + k];
        for (int o = 16; o > 0; o >>= 1) p += __shfl_down_sync(0xffffffffu, p, o);
        if (lane == 0) d_P[b * NCOMBO + c] = p;
    }
}

__global__ void k_graphsm() {
    int b = blockIdx.x, tid = threadIdx.x;
    __shared__ float Pb[NCOMBO];
    __shared__ float Wacc[NCOMBO];
    __shared__ float red[256];
    for (int i = tid; i < NCOMBO; i += 256) { Pb[i] = d_P[b * NCOMBO + i]; Wacc[i] = 0.f; }
    __syncthreads();
    int cid[4]; float sc[4]; float lmax = -1e30f;
#pragma unroll
    for (int j = 0; j < 4; j++) {
        int e = b * LL + tid + j * 256;
        cid[j] = d_combo[e];
        sc[j] = Pb[cid[j]];
        lmax = fmaxf(lmax, sc[j]);
    }
    red[tid] = lmax; __syncthreads();
    for (int s = 128; s > 0; s >>= 1) { if (tid < s) red[tid] = fmaxf(red[tid], red[tid + s]); __syncthreads(); }
    float bmax = red[0]; __syncthreads();
    float lsum = 0.f;
#pragma unroll
    for (int j = 0; j < 4; j++) { sc[j] = expf(sc[j] - bmax); lsum += sc[j]; }
    red[tid] = lsum; __syncthreads();
    for (int s = 128; s > 0; s >>= 1) { if (tid < s) red[tid] += red[tid + s]; __syncthreads(); }
    float inv = 1.f / red[0]; __syncthreads();
#pragma unroll
    for (int j = 0; j < 4; j++) atomicAdd(&Wacc[cid[j]], sc[j] * inv);
    __syncthreads();
    for (int i = tid; i < NCOMBO; i += 256) d_Wt[b * NCOMBO + i] = Wacc[i];
}

__global__ void k_upd() {
    int b = blockIdx.x, d = threadIdx.x;
    __shared__ float w[NCOMBO];
    for (int i = d; i < NCOMBO; i += blockDim.x) w[i] = d_Wt[b * NCOMBO + i];
    __syncthreads();
    if (d < DD) {
        float acc = 0.f;
        for (int c = 0; c < NCOMBO; c++) acc += w[c] * d_Rtab[c * DD + d];
        d_upd[b * DD + d] = acc;
    }
}

__global__ void k_ukum(const float* __restrict__ Wk, const float* __restrict__ Wm) {
    int id = blockIdx.x, d = threadIdx.x;
    __shared__ float s[DD];
    const float* srow = (id < BB) ? &d_upd[id * DD] : &d_embS[(id - BB) * DD];
    if (d < DD) s[d] = srow[d];
    __syncthreads();
    if (d < DD) {
        float ak = 0.f, am = 0.f;
        for (int k = 0; k < DD; k++) {
            float sv = s[k];
            ak += sv * Wk[(DD + k) * DD + d];
            am += sv * Wm[(DD + k) * DD + d];
        }
        d_UKall[id * DD + d] = ak;
        d_UMall[id * DD + d] = am;
    }
}

// ------------------------- weight packing -------------------------
__global__ void k_wcat(const float* __restrict__ Wk, const float* __restrict__ Wm,
                       const float* __restrict__ Wq) {
    int i = blockIdx.x * blockDim.x + threadIdx.x;
    if (i >= DD * 640) return;
    int k = i / 640, c = i % 640;
    float v = (c < DD) ? Wk[k * DD + c]
            : (c < 2 * DD) ? Wm[k * DD + (c - DD)]
            : (c < 3 * DD) ? Wq[k * DD + (c - 2 * DD)] : 0.f;
    d_Wcat[i] = v;
}

__global__ void k_wpad(const float* __restrict__ W, float* __restrict__ P) {
    int i = blockIdx.x * blockDim.x + threadIdx.x;
    if (i >= DD * 256) return;
    int k = i >> 8, c = i & 255;
    P[i] = (c < DD) ? W[k * DD + c] : 0.f;
}

// ------------------------- f32x2 packed GEMM: 128x128 tile, 8x8/thread -------------------------
__global__ __launch_bounds__(256, 2) void k_gemm2(
    int M, int Nreal, int K,
    const float* __restrict__ A, int lda,
    const float* __restrict__ B, int ldb,
    float* __restrict__ C, int ldc,
    const float* __restrict__ bias,
    const float* __restrict__ bnm, const float* __restrict__ bnr,
    const float* __restrict__ bng, const float* __restrict__ bnb) {
    __shared__ float As[8][128];
    __shared__ float Bs[8][128];
    int tid = threadIdx.x;
    int row0 = blockIdx.y * 128, col0 = blockIdx.x * 128;
    int ty = tid >> 4, tx = tid & 15;
    unsigned long long acc[8][4];
#pragma unroll
    for (int i = 0; i < 8; i++)
#pragma unroll
        for (int j = 0; j < 4; j++) acc[i][j] = 0ULL;
    int rowA = row0 + (tid >> 1);
    int kA = (tid & 1) * 4;
    int rowB = tid >> 5;
    int colB = (tid & 31) * 4;
    for (int k0 = 0; k0 < K; k0 += 8) {
        float4 av = *(const float4*)&A[(size_t)rowA * lda + k0 + kA];
        if (bnm) {
            int g = k0 + kA;
            av.x = fmaxf((av.x - bnm[g])     * bnr[g]     * bng[g]     + bnb[g],     0.f);
            av.y = fmaxf((av.y - bnm[g + 1]) * bnr[g + 1] * bng[g + 1] + bnb[g + 1], 0.f);
            av.z = fmaxf((av.z - bnm[g + 2]) * bnr[g + 2] * bng[g + 2] + bnb[g + 2], 0.f);
            av.w = fmaxf((av.w - bnm[g + 3]) * bnr[g + 3] * bng[g + 3] + bnb[g + 3], 0.f);
        }
        int m = tid >> 1;
        As[kA + 0][m] = av.x; As[kA + 1][m] = av.y;
        As[kA + 2][m] = av.z; As[kA + 3][m] = av.w;
        *(float4*)&Bs[rowB][colB] = *(const float4*)&B[(size_t)(k0 + rowB) * ldb + col0 + colB];
        __syncthreads();
#pragma unroll
        for (int kk = 0; kk < 8; kk++) {
            float4 a0 = *(const float4*)&As[kk][ty * 8];
            float4 a1 = *(const float4*)&As[kk][ty * 8 + 4];
            ulonglong2 b01 = *(const ulonglong2*)&Bs[kk][tx * 8];
            ulonglong2 b23 = *(const ulonglong2*)&Bs[kk][tx * 8 + 4];
            unsigned long long bb[4] = { b01.x, b01.y, b23.x, b23.y };
            unsigned long long a2[8];
            PACK2(a2[0], a0.x, a0.x); PACK2(a2[1], a0.y, a0.y);
            PACK2(a2[2], a0.z, a0.z); PACK2(a2[3], a0.w, a0.w);
            PACK2(a2[4], a1.x, a1.x); PACK2(a2[5], a1.y, a1.y);
            PACK2(a2[6], a1.z, a1.z); PACK2(a2[7], a1.w, a1.w);
#pragma unroll
            for (int i = 0; i < 8; i++) {
                FMA2(acc[i][0], a2[i], bb[0]);
                FMA2(acc[i][1], a2[i], bb[1]);
                FMA2(acc[i][2], a2[i], bb[2]);
                FMA2(acc[i][3], a2[i], bb[3]);
            }
        }
        __syncthreads();
    }
#pragma unroll
    for (int i = 0; i < 8; i++) {
        int r = row0 + ty * 8 + i;
        float* crow = &C[(size_t)r * ldc];
#pragma unroll
        for (int j = 0; j < 4; j++) {
            float lo, hi; UNPACK2(lo, hi, acc[i][j]);
            int c0 = col0 + tx * 8 + j * 2;
            if (c0 < Nreal)     crow[c0]     = lo + (bias ? bias[c0]     : 0.f);
            if (c0 + 1 < Nreal) crow[c0 + 1] = hi + (bias ? bias[c0 + 1] : 0.f);
        }
    }
}

// ------------------------- edge attention: scores + softmax denominators -------------------------
__global__ void k_D1(const int* __restrict__ ei, const int* __restrict__ ntp,
                     const float* __restrict__ bq, const float* __restrict__ bk) {
    int warp = (blockIdx.x * blockDim.x + threadIdx.x) >> 5;
    int lane = threadIdx.x & 31;
    if (warp >= TOTROWS) return;
    int i = warp;
    int s, dd, krow_idx;
    if (i < EE) { s = ei[i]; dd = ei[EE + i]; krow_idx = i >> 10; }
    else { int n = i - EE; s = n; dd = n; krow_idx = BB + ntp[n]; }
    const float* kadd = &d_UKall[krow_idx * DD];
    const float* qrow = &d_XKMQ[(size_t)s * 600 + 400];
    const float* krow = &d_XKMQ[(size_t)dd * 600];
    const float invs = 0.1414213562373095f;  // 1/sqrt(50)
#pragma unroll
    for (int h = 0; h < 4; h++) {
        float p = 0.f;
        if (lane < 25) {
            int d0 = h * 50 + lane * 2;
            float2 q2 = *(const float2*)(qrow + d0);
            float2 k2 = *(const float2*)(krow + d0);
            float2 a2 = *(const float2*)(kadd + d0);
            float2 bq2 = *(const float2*)(bq + d0);
            float2 bk2 = *(const float2*)(bk + d0);
            float qa = (q2.x + bq2.x) * invs, qb = (q2.y + bq2.y) * invs;
            float ka = k2.x + a2.x + bk2.x, kb = k2.y + a2.y + bk2.y;
            p = qa * ka + qb * kb;
        }
        for (int o = 16; o > 0; o >>= 1) p += __shfl_down_sync(0xffffffffu, p, o);
        if (lane == 0) {
            float exv = __expf(p);  // shift-invariant softmax; |p| << 1 so exp is safe
            d_ex[(size_t)i * 4 + h] = exv;
            atomicAdd(&d_den[s * 4 + h], exv);
        }
    }
}

// ------------------------- aggregation via dst-CSR (atomic-free) -------------------------
__global__ __launch_bounds__(256) void k_D2csr(const int* __restrict__ ei,
                                               const int* __restrict__ ntp,
                                               const float* __restrict__ bm) {
    int n = blockIdx.x;
    int beg = d_dstOff[n], end = d_dstOff[n + 1];
    int tid = threadIdx.x;
    __shared__ float s_al[64][4];
    __shared__ int s_j[64];
    __shared__ int s_u[64];
    float acc = 0.f;
    float bmv = (tid < DD) ? bm[tid] : 0.f;
    int h = tid / 50;
    for (int base = beg; base < end; base += 64) {
        int cnt = min(64, end - base);
        __syncthreads();
        if (tid < cnt) {
            int i = d_csr[base + tid];
            int s, j, u;
            if (i < EE) { s = ei[i]; j = s; u = i >> 10; }
            else { int nn = i - EE; s = nn; j = nn; u = BB + ntp[nn]; }
            s_j[tid] = j;
            s_u[tid] = u;
            float cs = (float)d_cntSrc[s];
#pragma unroll
            for (int hh = 0; hh < 4; hh++)
                s_al[tid][hh] = d_ex[(size_t)i * 4 + hh] / d_den[s * 4 + hh] * cs;
        }
        __syncthreads();
        if (tid < DD) {
            for (int r = 0; r < cnt; r++) {
                const float* mrow = &d_XKMQ[(size_t)s_j[r] * 600 + 200];
                const float* urow = &d_UMall[s_u[r] * DD];
                acc += s_al[r][h] * (mrow[tid] + urow[tid] + bmv);
            }
        }
    }
    if (tid < DD) d_aggr[(size_t)n * DD + tid] = acc;
}

// ------------------------- output BN stats -------------------------
__global__ void k_colstat() {
    int d = threadIdx.x;
    if (d >= DD) return;
    int r0 = blockIdx.x * 256;
    float s = 0.f, s2 = 0.f;
    for (int r = r0; r < r0 + 256; r++) {
        float v = d_Y1[(size_t)r * DD + d];
        s += v; s2 += v * v;
    }
    atomicAdd(&d_colsum[d], s);
    atomicAdd(&d_colsum2[d], s2);
}

__global__ void k_stat3() {
    int d = threadIdx.x;
    if (d >= DD) return;
    float m = d_colsum[d] / (float)NN;
    float var = d_colsum2[d] / (float)NN - m * m;
    d_bn3m[d] = m;
    d_bn3r[d] = rsqrtf(var + 1e-5f);
}

// ------------------------- launch -------------------------
extern "C" void kernel_launch(void* const* d_in, const int* in_sizes, int n_in,
                              void* d_out, int out_size) {
    const float* x    = (const float*)d_in[0];
    const float* sent = (const float*)d_in[2];
    const float* We1  = (const float*)d_in[3];
    const float* be1  = (const float*)d_in[4];
    const float* ge1  = (const float*)d_in[5];
    const float* bte1 = (const float*)d_in[6];
    const float* We2  = (const float*)d_in[7];
    const float* be2  = (const float*)d_in[8];
    const float* Wa1  = (const float*)d_in[9];
    const float* ba1  = (const float*)d_in[10];
    const float* ga1  = (const float*)d_in[11];
    const float* bta1 = (const float*)d_in[12];
    const float* Wa2  = (const float*)d_in[13];
    const float* ba2  = (const float*)d_in[14];
    const float* Watt = (const float*)d_in[15];
    const float* Wk   = (const float*)d_in[16];
    const float* bk   = (const float*)d_in[17];
    const float* Wm   = (const float*)d_in[18];
    const float* bm   = (const float*)d_in[19];
    const float* Wq   = (const float*)d_in[20];
    const float* bq   = (const float*)d_in[21];
    const float* Wo1  = (const float*)d_in[22];
    const float* bo1  = (const float*)d_in[23];
    const float* go1  = (const float*)d_in[24];
    const float* bto1 = (const float*)d_in[25];
    const float* Wo2  = (const float*)d_in[26];
    const float* bo2  = (const float*)d_in[27];
    const int* ei     = (const int*)d_in[28];
    const int* et     = (const int*)d_in[29];
    const int* ntp    = (const int*)d_in[30];
    float* out = (float*)d_out;

    void* tmp;
    cudaGetSymbolAddress(&tmp, d_Wcat);  float* pWcat = (float*)tmp;
    cudaGetSymbolAddress(&tmp, d_Wo1P);  float* pWo1P = (float*)tmp;
    cudaGetSymbolAddress(&tmp, d_Wo2P);  float* pWo2P = (float*)tmp;
    cudaGetSymbolAddress(&tmp, d_XKMQ);  float* pXKMQ = (float*)tmp;
    cudaGetSymbolAddress(&tmp, d_aggr);  float* pAggr = (float*)tmp;
    cudaGetSymbolAddress(&tmp, d_Y1);    float* pY1   = (float*)tmp;
    cudaGetSymbolAddress(&tmp, d_bn3m);  float* pb3m  = (float*)tmp;
    cudaGetSymbolAddress(&tmp, d_bn3r);  float* pb3r  = (float*)tmp;

    k_zero<<<1024, 256>>>();
    k_nodehist<<<NN / 256, 256>>>(ntp);
    k_edgehist<<<EE / 256, 256>>>(ei, et, ntp);
    k_scan<<<1, 1024>>>();
    k_csrfill<<<(TOTROWS + 255) / 256, 256>>>(ei);
    k_segsum3<<<400, 128>>>(x);
    k_meanT<<<(NT1 * DD + 255) / 256, 256>>>();
    k_tables<<<NCOMBO + NTY, 256>>>(We1, be1);
    k_bnstat1p<<<DD, 128>>>();
    k_emb<<<NCOMBO + NTY, 256>>>(We2, be2, ge1, bte1);
    k_h2pre<<<NCOMBO, 256>>>(Wa1, ba1);
    k_bnstat2p<<<DD, 128>>>();
    k_Rtab<<<NCOMBO, 256>>>(Wa2, ba2, ga1, bta1);
    k_q<<<BB, 256>>>(sent, Watt);
    k_P<<<BB, 256>>>();
    k_graphsm<<<BB, 256>>>();
    k_upd<<<BB, 256>>>();
    k_ukum<<<BB + NTY, 256>>>(Wk, Wm);
    k_wcat<<<(DD * 640 + 255) / 256, 256>>>(Wk, Wm, Wq);
    k_wpad<<<(DD * 256 + 255) / 256, 256>>>(Wo1, pWo1P);
    k_wpad<<<(DD * 256 + 255) / 256, 256>>>(Wo2, pWo2P);
    {   // XKMQ = x @ [Wk1|Wm1|Wq]  (51200 x 600 x 200)
        dim3 g(5, NN / 128);
        k_gemm2<<<g, 256>>>(NN, 600, DD, x, DD, pWcat, 640, pXKMQ, 600,
                            nullptr, nullptr, nullptr, nullptr, nullptr);
    }
    k_D1<<<(TOTROWS + 7) / 8, 256>>>(ei, ntp, bq, bk);
    k_D2csr<<<NN, 256>>>(ei, ntp, bm);
    {   // Y1 = aggr @ Wo1 + bo1
        dim3 g(2, NN / 128);
        k_gemm2<<<g, 256>>>(NN, DD, DD, pAggr, DD, pWo1P, 256, pY1, DD,
                            bo1, nullptr, nullptr, nullptr, nullptr);
    }
    k_colstat<<<NN / 256, 256>>>();
    k_stat3<<<1, 256>>>();
    {   // out = relu(bn(Y1)) @ Wo2 + bo2
        dim3 g(2, NN / 128);
        k_gemm2<<<g, 256>>>(NN, DD, DD, pY1, DD, pWo2P, 256, out, DD,
                            bo2, pb3m, pb3r, go1, bto1);
    }
}

// round 4
// speedup vs baseline: 1.5387x; 1.0484x over previous
#include <cuda_runtime.h>
#include <math.h>

#define DD 200
#define NTY 4
#define NET 38
#define NT1 39
#define BB 256
#define LL 1024
#define EE 262144
#define NN 51200
#define NCOMBO 608
#define TOTROWS (EE + NN)

// f32x2 packed-math helpers (FFMA2 — only reachable via PTX)
#define FMA2(d,a,b)  asm("fma.rn.f32x2 %0, %1, %2, %3;" : "=l"(d) : "l"(a), "l"(b), "l"(d))
#define PACK2(d,x,y) asm("mov.b64 %0, {%1, %2};" : "=l"(d) : "f"(x), "f"(y))
#define UNPACK2(x,y,d) asm("mov.b64 {%0, %1}, %2;" : "=f"(x), "=f"(y) : "l"(d))

// ------------------------- scratch (static device memory) -------------------------
__device__ float d_coeff[(size_t)NN * NT1];   // node-major: [n][etype]
__device__ float d_sums[NT1 * DD];
__device__ int   d_cntT[NT1];
__device__ int   d_cntE[NCOMBO];
__device__ int   d_cntN[NTY];
__device__ int   d_combo[EE];
__device__ int   d_cntSrc[NN];
__device__ int   d_dstCnt[NN];
__device__ int   d_dstOff[NN + 1];
__device__ int   d_cursor[NN];
__device__ int   d_csr[TOTROWS];
__device__ int   d_blkSum[50];
__device__ float d_meanT[NT1 * DD];
__device__ float d_preE[NCOMBO * DD];
__device__ float d_preS[NTY * DD];
__device__ float d_embE[NCOMBO * DD];
__device__ float d_embS[NTY * DD];
__device__ float d_h2[NCOMBO * DD];
__device__ float d_Rtab[NCOMBO * DD];
__device__ float d_bn1m[DD], d_bn1r[DD], d_bn2m[DD], d_bn2r[DD], d_bn3m[DD], d_bn3r[DD];
__device__ float d_qv[BB * DD];
__device__ float d_P[BB * NCOMBO];
__device__ float d_Wt[BB * NCOMBO];
__device__ float d_upd[BB * DD];
__device__ float d_UKall[(BB + NTY) * DD];
__device__ float d_UMall[(BB + NTY) * DD];
__device__ float d_Wcat[DD * 640];
__device__ float d_Wo1P[DD * 256];
__device__ float d_Wo2P[DD * 256];
__device__ float d_XKMQ[(size_t)NN * 600];    // per-node [XK | XM | XQ]
__device__ float d_ex[(size_t)TOTROWS * 4];
__device__ float d_den[NN * 4];
__device__ float d_aggr[(size_t)NN * DD];
__device__ float d_Y1[(size_t)NN * DD];
__device__ float d_colsum[DD], d_colsum2[DD];

// ------------------------- zero init -------------------------
__global__ void k_zero() {
    long long i0 = (long long)blockIdx.x * blockDim.x + threadIdx.x;
    long long st = (long long)gridDim.x * blockDim.x;
    for (long long i = i0; i < (long long)NT1 * NN; i += st) d_coeff[i] = 0.f;
    for (long long i = i0; i < (long long)NN * 4; i += st) d_den[i] = 0.f;
    for (long long i = i0; i < NT1 * DD; i += st) d_sums[i] = 0.f;
    for (long long i = i0; i < NCOMBO; i += st) d_cntE[i] = 0;
    for (long long i = i0; i < NT1; i += st) d_cntT[i] = 0;
    for (long long i = i0; i < NTY; i += st) d_cntN[i] = 0;
    for (long long i = i0; i < DD; i += st) { d_colsum[i] = 0.f; d_colsum2[i] = 0.f; }
}

// ------------------------- histograms -------------------------
__global__ void k_nodehist(const int* __restrict__ ntp) {
    int n = blockIdx.x * blockDim.x + threadIdx.x;
    if (n >= NN) return;
    d_cntSrc[n] = 1;                       // self loop (as src)
    d_dstCnt[n] = 1;                       // self loop (as dst)
    atomicAdd(&d_cntN[ntp[n]], 1);
}

__global__ void k_edgehist(const int* __restrict__ ei, const int* __restrict__ et,
                           const int* __restrict__ ntp) {
    int e = blockIdx.x * blockDim.x + threadIdx.x;
    if (e >= EE) return;
    int s  = ei[e];
    int dd = ei[EE + e];
    int t  = et[e];
    atomicAdd(&d_coeff[(size_t)dd * NT1 + t],  1.f);
    atomicAdd(&d_coeff[(size_t)s  * NT1 + t], -1.f);
    atomicAdd(&d_cntT[t], 1);
    int c = (t << 4) | (ntp[s] << 2) | ntp[dd];
    d_combo[e] = c;
    atomicAdd(&d_cntE[c], 1);
    atomicAdd(&d_cntSrc[s], 1);
    atomicAdd(&d_dstCnt[dd], 1);
}

// ------------------------- dst-CSR build (3-phase parallel scan) -------------------------
__global__ void k_scanA() {                  // 50 blocks x 1024: block sums
    __shared__ int sm[1024];
    int tid = threadIdx.x;
    sm[tid] = d_dstCnt[blockIdx.x * 1024 + tid];
    __syncthreads();
    for (int o = 512; o > 0; o >>= 1) {
        if (tid < o) sm[tid] += sm[tid + o];
        __syncthreads();
    }
    if (tid == 0) d_blkSum[blockIdx.x] = sm[0];
}

__global__ void k_scanB() {                  // 1 block x 64: scan of 50 block sums
    __shared__ int sm[64];
    int tid = threadIdx.x;
    int v = (tid < 50) ? d_blkSum[tid] : 0;
    sm[tid] = v;
    __syncthreads();
    for (int o = 1; o < 64; o <<= 1) {
        int t = (tid >= o) ? sm[tid - o] : 0;
        __syncthreads();
        sm[tid] += t;
        __syncthreads();
    }
    if (tid < 50) d_blkSum[tid] = sm[tid] - v;      // exclusive
    if (tid == 49) d_dstOff[NN] = sm[49];           // total
}

__global__ void k_scanC() {                  // 50 blocks x 1024: local scan + base
    __shared__ int sm[1024];
    int tid = threadIdx.x;
    int g = blockIdx.x * 1024 + tid;
    int v = d_dstCnt[g];
    sm[tid] = v;
    __syncthreads();
    for (int o = 1; o < 1024; o <<= 1) {
        int t = (tid >= o) ? sm[tid - o] : 0;
        __syncthreads();
        sm[tid] += t;
        __syncthreads();
    }
    int excl = sm[tid] - v + d_blkSum[blockIdx.x];
    d_dstOff[g] = excl;
    d_cursor[g] = excl;
}

__global__ void k_csrfill(const int* __restrict__ ei) {
    int i = blockIdx.x * blockDim.x + threadIdx.x;
    if (i >= TOTROWS) return;
    int dst = (i < EE) ? ei[EE + i] : (i - EE);
    int pos = atomicAdd(&d_cursor[dst], 1);
    d_csr[pos] = i;
}

// ------------------------- segment sums: dense f32x2, smem-duplicated coeffs -------------------------
__global__ __launch_bounds__(128) void k_segsum3(const float* __restrict__ x) {
    __shared__ unsigned long long cf2[128][NT1];
    int tid = threadIdx.x;
    int n0 = blockIdx.x * 128;
    for (int i = tid; i < 128 * NT1; i += 128) {
        float c = d_coeff[(size_t)(n0 + i / NT1) * NT1 + (i % NT1)];
        unsigned long long c2; PACK2(c2, c, c);
        cf2[i / NT1][i % NT1] = c2;
    }
    __syncthreads();
    if (tid < 100) {
        unsigned long long acc[NT1];
#pragma unroll
        for (int t = 0; t < NT1; t++) acc[t] = 0ULL;
        for (int nn = 0; nn < 128; nn++) {
            float2 xv = *(const float2*)&x[(size_t)(n0 + nn) * DD + tid * 2];
            unsigned long long xv2; PACK2(xv2, xv.x, xv.y);
#pragma unroll
            for (int t = 0; t < NT1; t++)
                FMA2(acc[t], cf2[nn][t], xv2);
        }
#pragma unroll
        for (int t = 0; t < NT1; t++) {
            float lo, hi; UNPACK2(lo, hi, acc[t]);
            if (lo != 0.f) atomicAdd(&d_sums[t * DD + tid * 2], lo);
            if (hi != 0.f) atomicAdd(&d_sums[t * DD + tid * 2 + 1], hi);
        }
    }
}

__global__ void k_meanT() {
    int i = blockIdx.x * blockDim.x + threadIdx.x;
    if (i >= NT1 * DD) return;
    int t = i / DD;
    float c = (float)d_cntT[t];
    if (c < 1.f) c = 1.f;
    d_meanT[i] = d_sums[i] / c;
}

// ------------------------- combo tables -------------------------
__global__ void k_tables(const float* __restrict__ We1, const float* __restrict__ be1) {
    int c = blockIdx.x, d = threadIdx.x;
    if (d >= DD) return;
    if (c < NCOMBO) {
        int t = c >> 4, a = (c >> 2) & 3, b = c & 3;
        d_preE[c * DD + d] = We1[t * DD + d] + We1[(NT1 + a) * DD + d]
                           + We1[(NT1 + NTY + b) * DD + d] + be1[d];
    } else {
        int t = c - NCOMBO;
        d_preS[t * DD + d] = We1[NET * DD + d] + We1[(NT1 + t) * DD + d]
                           + We1[(NT1 + NTY + t) * DD + d] + be1[d];
    }
}

__global__ void k_bnstat1p() {
    int d = blockIdx.x, tid = threadIdx.x;
    __shared__ double rs[128], rs2[128];
    double s = 0.0, s2 = 0.0;
    for (int c = tid; c < NCOMBO; c += 128) {
        double w = (double)d_cntE[c], v = (double)d_preE[c * DD + d];
        s += w * v; s2 += w * v * v;
    }
    if (tid < NTY) {
        double w = (double)d_cntN[tid], v = (double)d_preS[tid * DD + d];
        s += w * v; s2 += w * v * v;
    }
    rs[tid] = s; rs2[tid] = s2;
    __syncthreads();
    for (int o = 64; o > 0; o >>= 1) {
        if (tid < o) { rs[tid] += rs[tid + o]; rs2[tid] += rs2[tid + o]; }
        __syncthreads();
    }
    if (tid == 0) {
        double m = rs[0] / (double)TOTROWS;
        double var = rs2[0] / (double)TOTROWS - m * m;
        d_bn1m[d] = (float)m;
        d_bn1r[d] = rsqrtf((float)var + 1e-5f);
    }
}

__global__ void k_emb(const float* __restrict__ We2, const float* __restrict__ be2,
                      const float* __restrict__ g, const float* __restrict__ bt) {
    int c = blockIdx.x, d = threadIdx.x;
    __shared__ float a[DD];
    const float* srow = (c < NCOMBO) ? &d_preE[c * DD] : &d_preS[(c - NCOMBO) * DD];
    if (d < DD) {
        float v = (srow[d] - d_bn1m[d]) * d_bn1r[d] * g[d] + bt[d];
        a[d] = fmaxf(v, 0.f);
    }
    __syncthreads();
    if (d < DD) {
        float acc = 0.f;
        for (int k = 0; k < DD; k++) acc += a[k] * We2[k * DD + d];
        float* dst = (c < NCOMBO) ? &d_embE[c * DD] : &d_embS[(c - NCOMBO) * DD];
        dst[d] = acc + be2[d];
    }
}

__global__ void k_h2pre(const float* __restrict__ Wa1, const float* __restrict__ ba1) {
    int c = blockIdx.x, d = threadIdx.x;
    __shared__ float e[DD], mt[DD];
    int t = c >> 4;
    if (d < DD) { e[d] = d_embE[c * DD + d]; mt[d] = d_meanT[t * DD + d]; }
    __syncthreads();
    if (d < DD) {
        float acc = ba1[d];
        for (int k = 0; k < DD; k++) acc += e[k] * Wa1[k * DD + d];
        for (int k = 0; k < DD; k++) acc += mt[k] * Wa1[(DD + k) * DD + d];
        d_h2[c * DD + d] = acc;
    }
}

__global__ void k_bnstat2p() {
    int d = blockIdx.x, tid = threadIdx.x;
    __shared__ double rs[128], rs2[128];
    double s = 0.0, s2 = 0.0;
    for (int c = tid; c < NCOMBO; c += 128) {
        double w = (double)d_cntE[c], v = (double)d_h2[c * DD + d];
        s += w * v; s2 += w * v * v;
    }
    rs[tid] = s; rs2[tid] = s2;
    __syncthreads();
    for (int o = 64; o > 0; o >>= 1) {
        if (tid < o) { rs[tid] += rs[tid + o]; rs2[tid] += rs2[tid + o]; }
        __syncthreads();
    }
    if (tid == 0) {
        double m = rs[0] / (double)EE;
        double var = rs2[0] / (double)EE - m * m;
        d_bn2m[d] = (float)m;
        d_bn2r[d] = rsqrtf((float)var + 1e-5f);
    }
}

__global__ void k_Rtab(const float* __restrict__ Wa2, const float* __restrict__ ba2,
                       const float* __restrict__ g, const float* __restrict__ bt) {
    int c = blockIdx.x, d = threadIdx.x;
    __shared__ float a[DD];
    if (d < DD) {
        float v = (d_h2[c * DD + d] - d_bn2m[d]) * d_bn2r[d] * g[d] + bt[d];
        a[d] = fmaxf(v, 0.f);
    }
    __syncthreads();
    if (d < DD) {
        float acc = 0.f;
        for (int k = 0; k < DD; k++) acc += a[k] * Wa2[k * DD + d];
        d_Rtab[c * DD + d] = acc + ba2[d];
    }
}

// ------------------------- graph attention -------------------------
__global__ void k_q(const float* __restrict__ sent, const float* __restrict__ Watt) {
    int b = blockIdx.x, d = threadIdx.x;
    __shared__ float s[DD];
    if (d < DD) s[d] = sent[b * DD + d];
    __syncthreads();
    if (d < DD) {
        float acc = 0.f;
        for (int k = 0; k < DD; k++) acc += s[k] * Watt[k * DD + d];
        d_qv[b * DD + d] = acc;
    }
}

__global__ void k_P() {
    int b = blockIdx.x, tid = threadIdx.x, lane = tid & 31, w = tid >> 5;
    __shared__ float q[DD];
    for (int i = tid; i < DD; i += blockDim.x)
        q[i] = d_qv[b * DD + i] * 0.07071067811865475f;  // 1/sqrt(200)
    __syncthreads();
    for (int c = w; c < NCOMBO; c += 8) {
        float p = 0.f;
        for (int k = lane; k < DD; k += 32) p += q[k] * d_Rtab[c * DD + k];
        for (int o = 16; o > 0; o >>= 1) p += __shfl_down_sync(0xffffffffu, p, o);
        if (lane == 0) d_P[b * NCOMBO + c] = p;
    }
}

__global__ void k_graphsm() {
    int b = blockIdx.x, tid = threadIdx.x;
    __shared__ float Pb[NCOMBO];
    __shared__ float Wacc[NCOMBO];
    __shared__ float red[256];
    for (int i = tid; i < NCOMBO; i += 256) { Pb[i] = d_P[b * NCOMBO + i]; Wacc[i] = 0.f; }
    __syncthreads();
    int cid[4]; float sc[4]; float lmax = -1e30f;
#pragma unroll
    for (int j = 0; j < 4; j++) {
        int e = b * LL + tid + j * 256;
        cid[j] = d_combo[e];
        sc[j] = Pb[cid[j]];
        lmax = fmaxf(lmax, sc[j]);
    }
    red[tid] = lmax; __syncthreads();
    for (int s = 128; s > 0; s >>= 1) { if (tid < s) red[tid] = fmaxf(red[tid], red[tid + s]); __syncthreads(); }
    float bmax = red[0]; __syncthreads();
    float lsum = 0.f;
#pragma unroll
    for (int j = 0; j < 4; j++) { sc[j] = expf(sc[j] - bmax); lsum += sc[j]; }
    red[tid] = lsum; __syncthreads();
    for (int s = 128; s > 0; s >>= 1) { if (tid < s) red[tid] += red[tid + s]; __syncthreads(); }
    float inv = 1.f / red[0]; __syncthreads();
#pragma unroll
    for (int j = 0; j < 4; j++) atomicAdd(&Wacc[cid[j]], sc[j] * inv);
    __syncthreads();
    for (int i = tid; i < NCOMBO; i += 256) d_Wt[b * NCOMBO + i] = Wacc[i];
}

__global__ void k_upd() {
    int b = blockIdx.x, d = threadIdx.x;
    __shared__ float w[NCOMBO];
    for (int i = d; i < NCOMBO; i += blockDim.x) w[i] = d_Wt[b * NCOMBO + i];
    __syncthreads();
    if (d < DD) {
        float acc = 0.f;
        for (int c = 0; c < NCOMBO; c++) acc += w[c] * d_Rtab[c * DD + d];
        d_upd[b * DD + d] = acc;
    }
}

__global__ void k_ukum(const float* __restrict__ Wk, const float* __restrict__ Wm) {
    int id = blockIdx.x, d = threadIdx.x;
    __shared__ float s[DD];
    const float* srow = (id < BB) ? &d_upd[id * DD] : &d_embS[(id - BB) * DD];
    if (d < DD) s[d] = srow[d];
    __syncthreads();
    if (d < DD) {
        float ak = 0.f, am = 0.f;
        for (int k = 0; k < DD; k++) {
            float sv = s[k];
            ak += sv * Wk[(DD + k) * DD + d];
            am += sv * Wm[(DD + k) * DD + d];
        }
        d_UKall[id * DD + d] = ak;
        d_UMall[id * DD + d] = am;
    }
}

// ------------------------- weight packing -------------------------
__global__ void k_wcat(const float* __restrict__ Wk, const float* __restrict__ Wm,
                       const float* __restrict__ Wq) {
    int i = blockIdx.x * blockDim.x + threadIdx.x;
    if (i >= DD * 640) return;
    int k = i / 640, c = i % 640;
    float v = (c < DD) ? Wk[k * DD + c]
            : (c < 2 * DD) ? Wm[k * DD + (c - DD)]
            : (c < 3 * DD) ? Wq[k * DD + (c - 2 * DD)] : 0.f;
    d_Wcat[i] = v;
}

__global__ void k_wpad(const float* __restrict__ W, float* __restrict__ P) {
    int i = blockIdx.x * blockDim.x + threadIdx.x;
    if (i >= DD * 256) return;
    int k = i >> 8, c = i & 255;
    P[i] = (c < DD) ? W[k * DD + c] : 0.f;
}

// ------------------------- f32x2 packed GEMM: 128x128 tile, 8x8/thread -------------------------
// DOSTAT: fuse column sum/sumsq of C into d_colsum/d_colsum2.
template<int DOSTAT>
__global__ __launch_bounds__(256, 2) void k_gemm2(
    int M, int Nreal, int K,
    const float* __restrict__ A, int lda,
    const float* __restrict__ B, int ldb,
    float* __restrict__ C, int ldc,
    const float* __restrict__ bias,
    const float* __restrict__ bnm, const float* __restrict__ bnr,
    const float* __restrict__ bng, const float* __restrict__ bnb) {
    __shared__ float As[8][128];
    __shared__ float Bs[8][128];
    __shared__ float cs[128], cs2[128];
    int tid = threadIdx.x;
    int row0 = blockIdx.y * 128, col0 = blockIdx.x * 128;
    int ty = tid >> 4, tx = tid & 15;
    if (DOSTAT && tid < 128) { cs[tid] = 0.f; cs2[tid] = 0.f; }
    unsigned long long acc[8][4];
#pragma unroll
    for (int i = 0; i < 8; i++)
#pragma unroll
        for (int j = 0; j < 4; j++) acc[i][j] = 0ULL;
    int rowA = row0 + (tid >> 1);
    int kA = (tid & 1) * 4;
    int rowB = tid >> 5;
    int colB = (tid & 31) * 4;
    for (int k0 = 0; k0 < K; k0 += 8) {
        float4 av = *(const float4*)&A[(size_t)rowA * lda + k0 + kA];
        if (bnm) {
            int g = k0 + kA;
            av.x = fmaxf((av.x - bnm[g])     * bnr[g]     * bng[g]     + bnb[g],     0.f);
            av.y = fmaxf((av.y - bnm[g + 1]) * bnr[g + 1] * bng[g + 1] + bnb[g + 1], 0.f);
            av.z = fmaxf((av.z - bnm[g + 2]) * bnr[g + 2] * bng[g + 2] + bnb[g + 2], 0.f);
            av.w = fmaxf((av.w - bnm[g + 3]) * bnr[g + 3] * bng[g + 3] + bnb[g + 3], 0.f);
        }
        int m = tid >> 1;
        As[kA + 0][m] = av.x; As[kA + 1][m] = av.y;
        As[kA + 2][m] = av.z; As[kA + 3][m] = av.w;
        *(float4*)&Bs[rowB][colB] = *(const float4*)&B[(size_t)(k0 + rowB) * ldb + col0 + colB];
        __syncthreads();
#pragma unroll
        for (int kk = 0; kk < 8; kk++) {
            float4 a0 = *(const float4*)&As[kk][ty * 8];
            float4 a1 = *(const float4*)&As[kk][ty * 8 + 4];
            ulonglong2 b01 = *(const ulonglong2*)&Bs[kk][tx * 8];
            ulonglong2 b23 = *(const ulonglong2*)&Bs[kk][tx * 8 + 4];
            unsigned long long bb[4] = { b01.x, b01.y, b23.x, b23.y };
            unsigned long long a2[8];
            PACK2(a2[0], a0.x, a0.x); PACK2(a2[1], a0.y, a0.y);
            PACK2(a2[2], a0.z, a0.z); PACK2(a2[3], a0.w, a0.w);
            PACK2(a2[4], a1.x, a1.x); PACK2(a2[5], a1.y, a1.y);
            PACK2(a2[6], a1.z, a1.z); PACK2(a2[7], a1.w, a1.w);
#pragma unroll
            for (int i = 0; i < 8; i++) {
                FMA2(acc[i][0], a2[i], bb[0]);
                FMA2(acc[i][1], a2[i], bb[1]);
                FMA2(acc[i][2], a2[i], bb[2]);
                FMA2(acc[i][3], a2[i], bb[3]);
            }
        }
        __syncthreads();
    }
    float colS[8], colS2[8];
#pragma unroll
    for (int j = 0; j < 8; j++) { colS[j] = 0.f; colS2[j] = 0.f; }
#pragma unroll
    for (int i = 0; i < 8; i++) {
        int r = row0 + ty * 8 + i;
        float* crow = &C[(size_t)r * ldc];
#pragma unroll
        for (int j = 0; j < 4; j++) {
            float lo, hi; UNPACK2(lo, hi, acc[i][j]);
            int c0 = col0 + tx * 8 + j * 2;
            if (c0 < Nreal) {
                float v = lo + (bias ? bias[c0] : 0.f);
                crow[c0] = v;
                if (DOSTAT) { colS[j * 2] += v; colS2[j * 2] += v * v; }
            }
            if (c0 + 1 < Nreal) {
                float v = hi + (bias ? bias[c0 + 1] : 0.f);
                crow[c0 + 1] = v;
                if (DOSTAT) { colS[j * 2 + 1] += v; colS2[j * 2 + 1] += v * v; }
            }
        }
    }
    if (DOSTAT) {
        __syncthreads();
#pragma unroll
        for (int j = 0; j < 4; j++) {
            int lc = tx * 8 + j * 2;
            atomicAdd(&cs[lc],      colS[j * 2]);
            atomicAdd(&cs2[lc],     colS2[j * 2]);
            atomicAdd(&cs[lc + 1],  colS[j * 2 + 1]);
            atomicAdd(&cs2[lc + 1], colS2[j * 2 + 1]);
        }
        __syncthreads();
        if (tid < 128) {
            int gc = col0 + tid;
            if (gc < Nreal) {
                atomicAdd(&d_colsum[gc],  cs[tid]);
                atomicAdd(&d_colsum2[gc], cs2[tid]);
            }
        }
    }
}

// ------------------------- edge attention: scores + softmax denominators -------------------------
// One warp per row; 4 heads x 8-lane octets; full lane utilization.
__global__ void k_D1(const int* __restrict__ ei, const int* __restrict__ ntp,
                     const float* __restrict__ bq, const float* __restrict__ bk) {
    int warp = (blockIdx.x * blockDim.x + threadIdx.x) >> 5;
    int lane = threadIdx.x & 31;
    if (warp >= TOTROWS) return;
    int i = warp;
    int s, dd, kidx;
    if (i < EE) { s = ei[i]; dd = ei[EE + i]; kidx = i >> 10; }
    else { int n = i - EE; s = n; dd = n; kidx = BB + ntp[n]; }
    const float* kadd = &d_UKall[kidx * DD];
    const float* qrow = &d_XKMQ[(size_t)s * 600 + 400];
    const float* krow = &d_XKMQ[(size_t)dd * 600];
    const float invs = 0.1414213562373095f;  // 1/sqrt(50)
    int h = lane >> 3, r = lane & 7;
    float p = 0.f;
#pragma unroll
    for (int j = 0; j < 4; j++) {
        int idx = r + 8 * j;
        if (idx < 25) {
            int d0 = h * 50 + idx * 2;
            float2 q2  = *(const float2*)(qrow + d0);
            float2 k2  = *(const float2*)(krow + d0);
            float2 a2  = *(const float2*)(kadd + d0);
            float2 bq2 = *(const float2*)(bq + d0);
            float2 bk2 = *(const float2*)(bk + d0);
            p += ((q2.x + bq2.x) * invs) * (k2.x + a2.x + bk2.x)
               + ((q2.y + bq2.y) * invs) * (k2.y + a2.y + bk2.y);
        }
    }
    p += __shfl_down_sync(0xffffffffu, p, 4);
    p += __shfl_down_sync(0xffffffffu, p, 2);
    p += __shfl_down_sync(0xffffffffu, p, 1);
    if (r == 0) {
        float exv = __expf(p);   // shift-invariant softmax; |p| << 1 so exp is safe
        d_ex[(size_t)i * 4 + h] = exv;
        atomicAdd(&d_den[s * 4 + h], exv);
    }
}

// ------------------------- aggregation via dst-CSR (atomic-free) -------------------------
__global__ __launch_bounds__(256) void k_D2csr(const int* __restrict__ ei,
                                               const int* __restrict__ ntp,
                                               const float* __restrict__ bm) {
    int n = blockIdx.x;
    int beg = d_dstOff[n], end = d_dstOff[n + 1];
    int tid = threadIdx.x;
    __shared__ float s_al[64][4];
    __shared__ int s_j[64];
    __shared__ int s_u[64];
    float acc = 0.f;
    float bmv = (tid < DD) ? bm[tid] : 0.f;
    int h = tid / 50;
    for (int base = beg; base < end; base += 64) {
        int cnt = min(64, end - base);
        __syncthreads();
        if (tid < cnt) {
            int i = d_csr[base + tid];
            int s, j, u;
            if (i < EE) { s = ei[i]; j = s; u = i >> 10; }
            else { int nn = i - EE; s = nn; j = nn; u = BB + ntp[nn]; }
            s_j[tid] = j;
            s_u[tid] = u;
            float cs = (float)d_cntSrc[s];
#pragma unroll
            for (int hh = 0; hh < 4; hh++)
                s_al[tid][hh] = d_ex[(size_t)i * 4 + hh] / d_den[s * 4 + hh] * cs;
        }
        __syncthreads();
        if (tid < DD) {
            for (int r = 0; r < cnt; r++) {
                const float* mrow = &d_XKMQ[(size_t)s_j[r] * 600 + 200];
                const float* urow = &d_UMall[s_u[r] * DD];
                acc += s_al[r][h] * (mrow[tid] + urow[tid] + bmv);
            }
        }
    }
    if (tid < DD) d_aggr[(size_t)n * DD + tid] = acc;
}

__global__ void k_stat3() {
    int d = threadIdx.x;
    if (d >= DD) return;
    float m = d_colsum[d] / (float)NN;
    float var = d_colsum2[d] / (float)NN - m * m;
    d_bn3m[d] = m;
    d_bn3r[d] = rsqrtf(var + 1e-5f);
}

// ------------------------- launch -------------------------
extern "C" void kernel_launch(void* const* d_in, const int* in_sizes, int n_in,
                              void* d_out, int out_size) {
    const float* x    = (const float*)d_in[0];
    const float* sent = (const float*)d_in[2];
    const float* We1  = (const float*)d_in[3];
    const float* be1  = (const float*)d_in[4];
    const float* ge1  = (const float*)d_in[5];
    const float* bte1 = (const float*)d_in[6];
    const float* We2  = (const float*)d_in[7];
    const float* be2  = (const float*)d_in[8];
    const float* Wa1  = (const float*)d_in[9];
    const float* ba1  = (const float*)d_in[10];
    const float* ga1  = (const float*)d_in[11];
    const float* bta1 = (const float*)d_in[12];
    const float* Wa2  = (const float*)d_in[13];
    const float* ba2  = (const float*)d_in[14];
    const float* Watt = (const float*)d_in[15];
    const float* Wk   = (const float*)d_in[16];
    const float* bk   = (const float*)d_in[17];
    const float* Wm   = (const float*)d_in[18];
    const float* bm   = (const float*)d_in[19];
    const float* Wq   = (const float*)d_in[20];
    const float* bq   = (const float*)d_in[21];
    const float* Wo1  = (const float*)d_in[22];
    const float* bo1  = (const float*)d_in[23];
    const float* go1  = (const float*)d_in[24];
    const float* bto1 = (const float*)d_in[25];
    const float* Wo2  = (const float*)d_in[26];
    const float* bo2  = (const float*)d_in[27];
    const int* ei     = (const int*)d_in[28];
    const int* et     = (const int*)d_in[29];
    const int* ntp    = (const int*)d_in[30];
    float* out = (float*)d_out;

    void* tmp;
    cudaGetSymbolAddress(&tmp, d_Wcat);  float* pWcat = (float*)tmp;
    cudaGetSymbolAddress(&tmp, d_Wo1P);  float* pWo1P = (float*)tmp;
    cudaGetSymbolAddress(&tmp, d_Wo2P);  float* pWo2P = (float*)tmp;
    cudaGetSymbolAddress(&tmp, d_XKMQ);  float* pXKMQ = (float*)tmp;
    cudaGetSymbolAddress(&tmp, d_aggr);  float* pAggr = (float*)tmp;
    cudaGetSymbolAddress(&tmp, d_Y1);    float* pY1   = (float*)tmp;
    cudaGetSymbolAddress(&tmp, d_bn3m);  float* pb3m  = (float*)tmp;
    cudaGetSymbolAddress(&tmp, d_bn3r);  float* pb3r  = (float*)tmp;

    k_zero<<<1024, 256>>>();
    k_nodehist<<<NN / 256, 256>>>(ntp);
    k_edgehist<<<EE / 256, 256>>>(ei, et, ntp);
    k_scanA<<<50, 1024>>>();
    k_scanB<<<1, 64>>>();
    k_scanC<<<50, 1024>>>();
    k_csrfill<<<(TOTROWS + 255) / 256, 256>>>(ei);
    k_segsum3<<<400, 128>>>(x);
    k_meanT<<<(NT1 * DD + 255) / 256, 256>>>();
    k_tables<<<NCOMBO + NTY, 256>>>(We1, be1);
    k_bnstat1p<<<DD, 128>>>();
    k_emb<<<NCOMBO + NTY, 256>>>(We2, be2, ge1, bte1);
    k_h2pre<<<NCOMBO, 256>>>(Wa1, ba1);
    k_bnstat2p<<<DD, 128>>>();
    k_Rtab<<<NCOMBO, 256>>>(Wa2, ba2, ga1, bta1);
    k_q<<<BB, 256>>>(sent, Watt);
    k_P<<<BB, 256>>>();
    k_graphsm<<<BB, 256>>>();
    k_upd<<<BB, 256>>>();
    k_ukum<<<BB + NTY, 256>>>(Wk, Wm);
    k_wcat<<<(DD * 640 + 255) / 256, 256>>>(Wk, Wm, Wq);
    k_wpad<<<(DD * 256 + 255) / 256, 256>>>(Wo1, pWo1P);
    k_wpad<<<(DD * 256 + 255) / 256, 256>>>(Wo2, pWo2P);
    {   // XKMQ = x @ [Wk1|Wm1|Wq]  (51200 x 600 x 200)
        dim3 g(5, NN / 128);
        k_gemm2<0><<<g, 256>>>(NN, 600, DD, x, DD, pWcat, 640, pXKMQ, 600,
                               nullptr, nullptr, nullptr, nullptr, nullptr);
    }
    k_D1<<<(TOTROWS + 7) / 8, 256>>>(ei, ntp, bq, bk);
    k_D2csr<<<NN, 256>>>(ei, ntp, bm);
    {   // Y1 = aggr @ Wo1 + bo1  (+ fused column stats)
        dim3 g(2, NN / 128);
        k_gemm2<1><<<g, 256>>>(NN, DD, DD, pAggr, DD, pWo1P, 256, pY1, DD,
                               bo1, nullptr, nullptr, nullptr, nullptr);
    }
    k_stat3<<<1, 256>>>();
    {   // out = relu(bn(Y1)) @ Wo2 + bo2
        dim3 g(2, NN / 128);
        k_gemm2<0><<<g, 256>>>(NN, DD, DD, pY1, DD, pWo2P, 256, out, DD,
                               bo2, pb3m, pb3r, go1, bto1);
    }
}

// round 5
// speedup vs baseline: 2.0609x; 1.3393x over previous
#include <cuda_runtime.h>
#include <math.h>
#include <stdint.h>

#define DD 200
#define NTY 4
#define NET 38
#define NT1 39
#define BB 256
#define LL 1024
#define EE 262144
#define NN 51200
#define NCOMBO 608
#define TOTROWS (EE + NN)

// f32x2 packed-math helpers (FFMA2 — only reachable via PTX)
#define FMA2(d,a,b)  asm("fma.rn.f32x2 %0, %1, %2, %3;" : "=l"(d) : "l"(a), "l"(b), "l"(d))
#define PACK2(d,x,y) asm("mov.b64 %0, {%1, %2};" : "=l"(d) : "f"(x), "f"(y))
#define UNPACK2(x,y,d) asm("mov.b64 {%0, %1}, %2;" : "=f"(x), "=f"(y) : "l"(d))

#define CVT_TF32(u,f) asm("cvt.rna.tf32.f32 %0, %1;" : "=r"(u) : "f"(f))
#define MMA_TF32(c0,c1,c2,c3,a0,a1,a2,a3,b0,b1) \
  asm("mma.sync.aligned.m16n8k8.row.col.f32.tf32.tf32.f32 " \
      "{%0,%1,%2,%3},{%4,%5,%6,%7},{%8,%9},{%0,%1,%2,%3};" \
      : "+f"(c0),"+f"(c1),"+f"(c2),"+f"(c3) \
      : "r"(a0),"r"(a1),"r"(a2),"r"(a3),"r"(b0),"r"(b1))

// ------------------------- scratch (static device memory) -------------------------
__device__ float d_coeff[(size_t)NN * NT1];   // node-major: [n][etype]
__device__ float d_sums[NT1 * DD];
__device__ int   d_cntT[NT1];
__device__ int   d_cntE[NCOMBO];
__device__ int   d_cntN[NTY];
__device__ int   d_combo[EE];
__device__ int   d_cntSrc[NN];
__device__ int   d_dstCnt[NN];
__device__ int   d_dstOff[NN + 1];
__device__ int   d_cursor[NN];
__device__ int   d_csr[TOTROWS];
__device__ int   d_blkSum[50];
__device__ float d_meanT[NT1 * DD];
__device__ float d_preE[NCOMBO * DD];
__device__ float d_preS[NTY * DD];
__device__ float d_embE[NCOMBO * DD];
__device__ float d_embS[NTY * DD];
__device__ float d_h2[NCOMBO * DD];
__device__ float d_Rtab[NCOMBO * DD];
__device__ float d_bn1m[DD], d_bn1r[DD], d_bn2m[DD], d_bn2r[DD], d_bn3m[DD], d_bn3r[DD];
__device__ float d_qv[BB * DD];
__device__ float d_P[BB * NCOMBO];
__device__ float d_Wt[BB * NCOMBO];
__device__ float d_upd[BB * DD];
__device__ float d_UKall[(BB + NTY) * DD];
__device__ float d_UMall[(BB + NTY) * DD];
__device__ float d_Wcat[DD * 640];
__device__ float d_Wo1P[DD * 256];
__device__ float d_Wo2P[DD * 256];
__device__ float d_XKMQ[(size_t)NN * 600];    // per-node [XK | XM | XQ]
__device__ float d_ex[(size_t)TOTROWS * 4];
__device__ float d_den[NN * 4];
__device__ float d_aggr[(size_t)NN * DD];
__device__ float d_Y1[(size_t)NN * DD];
__device__ float d_colsum[DD], d_colsum2[DD];

// ------------------------- zero init -------------------------
__global__ void k_zero() {
    long long i0 = (long long)blockIdx.x * blockDim.x + threadIdx.x;
    long long st = (long long)gridDim.x * blockDim.x;
    for (long long i = i0; i < (long long)NT1 * NN; i += st) d_coeff[i] = 0.f;
    for (long long i = i0; i < (long long)NN * 4; i += st) d_den[i] = 0.f;
    for (long long i = i0; i < NT1 * DD; i += st) d_sums[i] = 0.f;
    for (long long i = i0; i < NCOMBO; i += st) d_cntE[i] = 0;
    for (long long i = i0; i < NT1; i += st) d_cntT[i] = 0;
    for (long long i = i0; i < NTY; i += st) d_cntN[i] = 0;
    for (long long i = i0; i < DD; i += st) { d_colsum[i] = 0.f; d_colsum2[i] = 0.f; }
}

// ------------------------- histograms -------------------------
__global__ void k_nodehist(const int* __restrict__ ntp) {
    int n = blockIdx.x * blockDim.x + threadIdx.x;
    if (n >= NN) return;
    d_cntSrc[n] = 1;
    d_dstCnt[n] = 1;
    atomicAdd(&d_cntN[ntp[n]], 1);
}

__global__ void k_edgehist(const int* __restrict__ ei, const int* __restrict__ et,
                           const int* __restrict__ ntp) {
    int e = blockIdx.x * blockDim.x + threadIdx.x;
    if (e >= EE) return;
    int s  = ei[e];
    int dd = ei[EE + e];
    int t  = et[e];
    atomicAdd(&d_coeff[(size_t)dd * NT1 + t],  1.f);
    atomicAdd(&d_coeff[(size_t)s  * NT1 + t], -1.f);
    atomicAdd(&d_cntT[t], 1);
    int c = (t << 4) | (ntp[s] << 2) | ntp[dd];
    d_combo[e] = c;
    atomicAdd(&d_cntE[c], 1);
    atomicAdd(&d_cntSrc[s], 1);
    atomicAdd(&d_dstCnt[dd], 1);
}

// ------------------------- dst-CSR build (3-phase parallel scan) -------------------------
__global__ void k_scanA() {
    __shared__ int sm[1024];
    int tid = threadIdx.x;
    sm[tid] = d_dstCnt[blockIdx.x * 1024 + tid];
    __syncthreads();
    for (int o = 512; o > 0; o >>= 1) {
        if (tid < o) sm[tid] += sm[tid + o];
        __syncthreads();
    }
    if (tid == 0) d_blkSum[blockIdx.x] = sm[0];
}

__global__ void k_scanB() {
    __shared__ int sm[64];
    int tid = threadIdx.x;
    int v = (tid < 50) ? d_blkSum[tid] : 0;
    sm[tid] = v;
    __syncthreads();
    for (int o = 1; o < 64; o <<= 1) {
        int t = (tid >= o) ? sm[tid - o] : 0;
        __syncthreads();
        sm[tid] += t;
        __syncthreads();
    }
    if (tid < 50) d_blkSum[tid] = sm[tid] - v;
    if (tid == 49) d_dstOff[NN] = sm[49];
}

__global__ void k_scanC() {
    __shared__ int sm[1024];
    int tid = threadIdx.x;
    int g = blockIdx.x * 1024 + tid;
    int v = d_dstCnt[g];
    sm[tid] = v;
    __syncthreads();
    for (int o = 1; o < 1024; o <<= 1) {
        int t = (tid >= o) ? sm[tid - o] : 0;
        __syncthreads();
        sm[tid] += t;
        __syncthreads();
    }
    int excl = sm[tid] - v + d_blkSum[blockIdx.x];
    d_dstOff[g] = excl;
    d_cursor[g] = excl;
}

__global__ void k_csrfill(const int* __restrict__ ei) {
    int i = blockIdx.x * blockDim.x + threadIdx.x;
    if (i >= TOTROWS) return;
    int dst = (i < EE) ? ei[EE + i] : (i - EE);
    int pos = atomicAdd(&d_cursor[dst], 1);
    d_csr[pos] = i;
}

// ------------------------- segment sums: dense f32x2, smem-duplicated coeffs -------------------------
__global__ __launch_bounds__(128) void k_segsum3(const float* __restrict__ x) {
    __shared__ unsigned long long cf2[128][NT1];
    int tid = threadIdx.x;
    int n0 = blockIdx.x * 128;
    for (int i = tid; i < 128 * NT1; i += 128) {
        float c = d_coeff[(size_t)(n0 + i / NT1) * NT1 + (i % NT1)];
        unsigned long long c2; PACK2(c2, c, c);
        cf2[i / NT1][i % NT1] = c2;
    }
    __syncthreads();
    if (tid < 100) {
        unsigned long long acc[NT1];
#pragma unroll
        for (int t = 0; t < NT1; t++) acc[t] = 0ULL;
        for (int nn = 0; nn < 128; nn++) {
            float2 xv = *(const float2*)&x[(size_t)(n0 + nn) * DD + tid * 2];
            unsigned long long xv2; PACK2(xv2, xv.x, xv.y);
#pragma unroll
            for (int t = 0; t < NT1; t++)
                FMA2(acc[t], cf2[nn][t], xv2);
        }
#pragma unroll
        for (int t = 0; t < NT1; t++) {
            float lo, hi; UNPACK2(lo, hi, acc[t]);
            if (lo != 0.f) atomicAdd(&d_sums[t * DD + tid * 2], lo);
            if (hi != 0.f) atomicAdd(&d_sums[t * DD + tid * 2 + 1], hi);
        }
    }
}

__global__ void k_meanT() {
    int i = blockIdx.x * blockDim.x + threadIdx.x;
    if (i >= NT1 * DD) return;
    int t = i / DD;
    float c = (float)d_cntT[t];
    if (c < 1.f) c = 1.f;
    d_meanT[i] = d_sums[i] / c;
}

// ------------------------- combo tables -------------------------
__global__ void k_tables(const float* __restrict__ We1, const float* __restrict__ be1) {
    int c = blockIdx.x, d = threadIdx.x;
    if (d >= DD) return;
    if (c < NCOMBO) {
        int t = c >> 4, a = (c >> 2) & 3, b = c & 3;
        d_preE[c * DD + d] = We1[t * DD + d] + We1[(NT1 + a) * DD + d]
                           + We1[(NT1 + NTY + b) * DD + d] + be1[d];
    } else {
        int t = c - NCOMBO;
        d_preS[t * DD + d] = We1[NET * DD + d] + We1[(NT1 + t) * DD + d]
                           + We1[(NT1 + NTY + t) * DD + d] + be1[d];
    }
}

__global__ void k_bnstat1p() {
    int d = blockIdx.x, tid = threadIdx.x;
    __shared__ double rs[128], rs2[128];
    double s = 0.0, s2 = 0.0;
    for (int c = tid; c < NCOMBO; c += 128) {
        double w = (double)d_cntE[c], v = (double)d_preE[c * DD + d];
        s += w * v; s2 += w * v * v;
    }
    if (tid < NTY) {
        double w = (double)d_cntN[tid], v = (double)d_preS[tid * DD + d];
        s += w * v; s2 += w * v * v;
    }
    rs[tid] = s; rs2[tid] = s2;
    __syncthreads();
    for (int o = 64; o > 0; o >>= 1) {
        if (tid < o) { rs[tid] += rs[tid + o]; rs2[tid] += rs2[tid + o]; }
        __syncthreads();
    }
    if (tid == 0) {
        double m = rs[0] / (double)TOTROWS;
        double var = rs2[0] / (double)TOTROWS - m * m;
        d_bn1m[d] = (float)m;
        d_bn1r[d] = rsqrtf((float)var + 1e-5f);
    }
}

__global__ void k_emb(const float* __restrict__ We2, const float* __restrict__ be2,
                      const float* __restrict__ g, const float* __restrict__ bt) {
    int c = blockIdx.x, d = threadIdx.x;
    __shared__ float a[DD];
    const float* srow = (c < NCOMBO) ? &d_preE[c * DD] : &d_preS[(c - NCOMBO) * DD];
    if (d < DD) {
        float v = (srow[d] - d_bn1m[d]) * d_bn1r[d] * g[d] + bt[d];
        a[d] = fmaxf(v, 0.f);
    }
    __syncthreads();
    if (d < DD) {
        float acc = 0.f;
        for (int k = 0; k < DD; k++) acc += a[k] * We2[k * DD + d];
        float* dst = (c < NCOMBO) ? &d_embE[c * DD] : &d_embS[(c - NCOMBO) * DD];
        dst[d] = acc + be2[d];
    }
}

__global__ void k_h2pre(const float* __restrict__ Wa1, const float* __restrict__ ba1) {
    int c = blockIdx.x, d = threadIdx.x;
    __shared__ float e[DD], mt[DD];
    int t = c >> 4;
    if (d < DD) { e[d] = d_embE[c * DD + d]; mt[d] = d_meanT[t * DD + d]; }
    __syncthreads();
    if (d < DD) {
        float acc = ba1[d];
        for (int k = 0; k < DD; k++) acc += e[k] * Wa1[k * DD + d];
        for (int k = 0; k < DD; k++) acc += mt[k] * Wa1[(DD + k) * DD + d];
        d_h2[c * DD + d] = acc;
    }
}

__global__ void k_bnstat2p() {
    int d = blockIdx.x, tid = threadIdx.x;
    __shared__ double rs[128], rs2[128];
    double s = 0.0, s2 = 0.0;
    for (int c = tid; c < NCOMBO; c += 128) {
        double w = (double)d_cntE[c], v = (double)d_h2[c * DD + d];
        s += w * v; s2 += w * v * v;
    }
    rs[tid] = s; rs2[tid] = s2;
    __syncthreads();
    for (int o = 64; o > 0; o >>= 1) {
        if (tid < o) { rs[tid] += rs[tid + o]; rs2[tid] += rs2[tid + o]; }
        __syncthreads();
    }
    if (tid == 0) {
        double m = rs[0] / (double)EE;
        double var = rs2[0] / (double)EE - m * m;
        d_bn2m[d] = (float)m;
        d_bn2r[d] = rsqrtf((float)var + 1e-5f);
    }
}

__global__ void k_Rtab(const float* __restrict__ Wa2, const float* __restrict__ ba2,
                       const float* __restrict__ g, const float* __restrict__ bt) {
    int c = blockIdx.x, d = threadIdx.x;
    __shared__ float a[DD];
    if (d < DD) {
        float v = (d_h2[c * DD + d] - d_bn2m[d]) * d_bn2r[d] * g[d] + bt[d];
        a[d] = fmaxf(v, 0.f);
    }
    __syncthreads();
    if (d < DD) {
        float acc = 0.f;
        for (int k = 0; k < DD; k++) acc += a[k] * Wa2[k * DD + d];
        d_Rtab[c * DD + d] = acc + ba2[d];
    }
}

// ------------------------- graph attention -------------------------
__global__ void k_q(const float* __restrict__ sent, const float* __restrict__ Watt) {
    int b = blockIdx.x, d = threadIdx.x;
    __shared__ float s[DD];
    if (d < DD) s[d] = sent[b * DD + d];
    __syncthreads();
    if (d < DD) {
        float acc = 0.f;
        for (int k = 0; k < DD; k++) acc += s[k] * Watt[k * DD + d];
        d_qv[b * DD + d] = acc;
    }
}

__global__ void k_P() {
    int b = blockIdx.x, tid = threadIdx.x, lane = tid & 31, w = tid >> 5;
    __shared__ float q[DD];
    for (int i = tid; i < DD; i += blockDim.x)
        q[i] = d_qv[b * DD + i] * 0.07071067811865475f;
    __syncthreads();
    for (int c = w; c < NCOMBO; c += 8) {
        float p = 0.f;
        for (int k = lane; k < DD; k += 32) p += q[k] * d_Rtab[c * DD + k];
        for (int o = 16; o > 0; o >>= 1) p += __shfl_down_sync(0xffffffffu, p, o);
        if (lane == 0) d_P[b * NCOMBO + c] = p;
    }
}

__global__ void k_graphsm() {
    int b = blockIdx.x, tid = threadIdx.x;
    __shared__ float Pb[NCOMBO];
    __shared__ float Wacc[NCOMBO];
    __shared__ float red[256];
    for (int i = tid; i < NCOMBO; i += 256) { Pb[i] = d_P[b * NCOMBO + i]; Wacc[i] = 0.f; }
    __syncthreads();
    int cid[4]; float sc[4]; float lmax = -1e30f;
#pragma unroll
    for (int j = 0; j < 4; j++) {
        int e = b * LL + tid + j * 256;
        cid[j] = d_combo[e];
        sc[j] = Pb[cid[j]];
        lmax = fmaxf(lmax, sc[j]);
    }
    red[tid] = lmax; __syncthreads();
    for (int s = 128; s > 0; s >>= 1) { if (tid < s) red[tid] = fmaxf(red[tid], red[tid + s]); __syncthreads(); }
    float bmax = red[0]; __syncthreads();
    float lsum = 0.f;
#pragma unroll
    for (int j = 0; j < 4; j++) { sc[j] = expf(sc[j] - bmax); lsum += sc[j]; }
    red[tid] = lsum; __syncthreads();
    for (int s = 128; s > 0; s >>= 1) { if (tid < s) red[tid] += red[tid + s]; __syncthreads(); }
    float inv = 1.f / red[0]; __syncthreads();
#pragma unroll
    for (int j = 0; j < 4; j++) atomicAdd(&Wacc[cid[j]], sc[j] * inv);
    __syncthreads();
    for (int i = tid; i < NCOMBO; i += 256) d_Wt[b * NCOMBO + i] = Wacc[i];
}

__global__ void k_upd() {
    int b = blockIdx.x, d = threadIdx.x;
    __shared__ float w[NCOMBO];
    for (int i = d; i < NCOMBO; i += blockDim.x) w[i] = d_Wt[b * NCOMBO + i];
    __syncthreads();
    if (d < DD) {
        float acc = 0.f;
        for (int c = 0; c < NCOMBO; c++) acc += w[c] * d_Rtab[c * DD + d];
        d_upd[b * DD + d] = acc;
    }
}

__global__ void k_ukum(const float* __restrict__ Wk, const float* __restrict__ Wm) {
    int id = blockIdx.x, d = threadIdx.x;
    __shared__ float s[DD];
    const float* srow = (id < BB) ? &d_upd[id * DD] : &d_embS[(id - BB) * DD];
    if (d < DD) s[d] = srow[d];
    __syncthreads();
    if (d < DD) {
        float ak = 0.f, am = 0.f;
        for (int k = 0; k < DD; k++) {
            float sv = s[k];
            ak += sv * Wk[(DD + k) * DD + d];
            am += sv * Wm[(DD + k) * DD + d];
        }
        d_UKall[id * DD + d] = ak;
        d_UMall[id * DD + d] = am;
    }
}

// ------------------------- weight packing -------------------------
__global__ void k_wcat(const float* __restrict__ Wk, const float* __restrict__ Wm,
                       const float* __restrict__ Wq) {
    int i = blockIdx.x * blockDim.x + threadIdx.x;
    if (i >= DD * 640) return;
    int k = i / 640, c = i % 640;
    float v = (c < DD) ? Wk[k * DD + c]
            : (c < 2 * DD) ? Wm[k * DD + (c - DD)]
            : (c < 3 * DD) ? Wq[k * DD + (c - 2 * DD)] : 0.f;
    d_Wcat[i] = v;
}

__global__ void k_wpad(const float* __restrict__ W, float* __restrict__ P) {
    int i = blockIdx.x * blockDim.x + threadIdx.x;
    if (i >= DD * 256) return;
    int k = i >> 8, c = i & 255;
    P[i] = (c < DD) ? W[k * DD + c] : 0.f;
}

// ------------------------- tf32 tensor-core GEMM: 128x128 tile, 8 warps (2x4) -------------------------
// C[M,Nreal] = op(A[M,K]) @ B[K,ldb] (+bias); op = optional BN+relu on A.
// DOSTAT: fuse column sum/sumsq of C into d_colsum/d_colsum2.
template<int DOSTAT>
__global__ __launch_bounds__(256, 2) void k_gemmT(
    int M, int Nreal, int K,
    const float* __restrict__ A, int lda,
    const float* __restrict__ B, int ldb,
    float* __restrict__ C, int ldc,
    const float* __restrict__ bias,
    const float* __restrict__ bnm, const float* __restrict__ bnr,
    const float* __restrict__ bng, const float* __restrict__ bnb) {
    __shared__ uint32_t As[8][132];   // As[k][m], padded stride vs bank conflicts
    __shared__ uint32_t Bs[8][132];   // Bs[k][n]
    __shared__ float cs[128], cs2[128];
    int tid = threadIdx.x;
    int lane = tid & 31, warp = tid >> 5;
    int wm = warp >> 2, wn = warp & 3;            // 2 x 4 warp grid
    int gid = lane >> 2, tg = lane & 3;
    int row0 = blockIdx.y * 128, col0 = blockIdx.x * 128;
    if (DOSTAT && tid < 128) { cs[tid] = 0.f; cs2[tid] = 0.f; }

    float acc[4][4][4];
#pragma unroll
    for (int mt = 0; mt < 4; mt++)
#pragma unroll
        for (int nt = 0; nt < 4; nt++)
#pragma unroll
            for (int r = 0; r < 4; r++) acc[mt][nt][r] = 0.f;

    int rowA = row0 + (tid >> 1);
    int kA = (tid & 1) * 4;
    int rowB = tid >> 5;
    int colB = (tid & 31) * 4;
    int m0 = wm * 64, n0 = wn * 32;

    for (int k0 = 0; k0 < K; k0 += 8) {
        float4 av = *(const float4*)&A[(size_t)rowA * lda + k0 + kA];
        if (bnm) {
            int g = k0 + kA;
            av.x = fmaxf((av.x - bnm[g])     * bnr[g]     * bng[g]     + bnb[g],     0.f);
            av.y = fmaxf((av.y - bnm[g + 1]) * bnr[g + 1] * bng[g + 1] + bnb[g + 1], 0.f);
            av.z = fmaxf((av.z - bnm[g + 2]) * bnr[g + 2] * bng[g + 2] + bnb[g + 2], 0.f);
            av.w = fmaxf((av.w - bnm[g + 3]) * bnr[g + 3] * bng[g + 3] + bnb[g + 3], 0.f);
        }
        uint32_t u0, u1, u2, u3;
        CVT_TF32(u0, av.x); CVT_TF32(u1, av.y); CVT_TF32(u2, av.z); CVT_TF32(u3, av.w);
        int m = tid >> 1;
        As[kA + 0][m] = u0; As[kA + 1][m] = u1; As[kA + 2][m] = u2; As[kA + 3][m] = u3;
        float4 bv = *(const float4*)&B[(size_t)(k0 + rowB) * ldb + col0 + colB];
        uint32_t w0, w1, w2, w3;
        CVT_TF32(w0, bv.x); CVT_TF32(w1, bv.y); CVT_TF32(w2, bv.z); CVT_TF32(w3, bv.w);
        Bs[rowB][colB] = w0; Bs[rowB][colB + 1] = w1;
        Bs[rowB][colB + 2] = w2; Bs[rowB][colB + 3] = w3;
        __syncthreads();

        uint32_t af[4][4], bf[4][2];
#pragma unroll
        for (int mt = 0; mt < 4; mt++) {
            int mb = m0 + mt * 16 + gid;
            af[mt][0] = As[tg][mb];
            af[mt][1] = As[tg][mb + 8];
            af[mt][2] = As[tg + 4][mb];
            af[mt][3] = As[tg + 4][mb + 8];
        }
#pragma unroll
        for (int nt = 0; nt < 4; nt++) {
            int nb = n0 + nt * 8 + gid;
            bf[nt][0] = Bs[tg][nb];
            bf[nt][1] = Bs[tg + 4][nb];
        }
#pragma unroll
        for (int mt = 0; mt < 4; mt++)
#pragma unroll
            for (int nt = 0; nt < 4; nt++)
                MMA_TF32(acc[mt][nt][0], acc[mt][nt][1], acc[mt][nt][2], acc[mt][nt][3],
                         af[mt][0], af[mt][1], af[mt][2], af[mt][3],
                         bf[nt][0], bf[nt][1]);
        __syncthreads();
    }

    // epilogue: c0 @(r, c), c1 @(r, c+1), c2 @(r+8, c), c3 @(r+8, c+1)
    float colS[4][2], colS2[4][2];
#pragma unroll
    for (int nt = 0; nt < 4; nt++) { colS[nt][0] = colS[nt][1] = 0.f; colS2[nt][0] = colS2[nt][1] = 0.f; }
#pragma unroll
    for (int mt = 0; mt < 4; mt++) {
        int r = row0 + m0 + mt * 16 + gid;
#pragma unroll
        for (int nt = 0; nt < 4; nt++) {
            int c = col0 + n0 + nt * 8 + tg * 2;
            float b0 = bias ? bias[c]     : 0.f;   // c < 256-pad region always readable (padded weights); real guard below
            float b1 = bias ? ((c + 1 < Nreal) ? bias[c + 1] : 0.f) : 0.f;
            if (c < Nreal)     b0 = bias ? bias[c] : 0.f; else b0 = 0.f;
            float v0 = acc[mt][nt][0] + b0;
            float v1 = acc[mt][nt][1] + b1;
            float v2 = acc[mt][nt][2] + b0;
            float v3 = acc[mt][nt][3] + b1;
            float* cr0 = &C[(size_t)r * ldc];
            float* cr1 = &C[(size_t)(r + 8) * ldc];
            if (c < Nreal)     { cr0[c] = v0; cr1[c] = v2; }
            if (c + 1 < Nreal) { cr0[c + 1] = v1; cr1[c + 1] = v3; }
            if (DOSTAT) {
                colS[nt][0]  += v0 + v2;
                colS2[nt][0] += v0 * v0 + v2 * v2;
                colS[nt][1]  += v1 + v3;
                colS2[nt][1] += v1 * v1 + v3 * v3;
            }
        }
    }
    if (DOSTAT) {
        // reduce over gid (lanes strided by 4) so lanes 0..3 hold per-column totals
#pragma unroll
        for (int nt = 0; nt < 4; nt++) {
#pragma unroll
            for (int p = 0; p < 2; p++) {
                float a = colS[nt][p], b = colS2[nt][p];
                for (int o = 16; o >= 4; o >>= 1) {
                    a += __shfl_down_sync(0xffffffffu, a, o);
                    b += __shfl_down_sync(0xffffffffu, b, o);
                }
                colS[nt][p] = a; colS2[nt][p] = b;
            }
        }
        __syncthreads();
        if (gid == 0) {
#pragma unroll
            for (int nt = 0; nt < 4; nt++) {
                int lc = n0 + nt * 8 + tg * 2;
                atomicAdd(&cs[lc],      colS[nt][0]);
                atomicAdd(&cs2[lc],     colS2[nt][0]);
                atomicAdd(&cs[lc + 1],  colS[nt][1]);
                atomicAdd(&cs2[lc + 1], colS2[nt][1]);
            }
        }
        __syncthreads();
        if (tid < 128) {
            int gc = col0 + tid;
            if (gc < Nreal) {
                atomicAdd(&d_colsum[gc],  cs[tid]);
                atomicAdd(&d_colsum2[gc], cs2[tid]);
            }
        }
    }
}

// ------------------------- edge attention: scores + softmax denominators -------------------------
__global__ void k_D1(const int* __restrict__ ei, const int* __restrict__ ntp,
                     const float* __restrict__ bq, const float* __restrict__ bk) {
    int warp = (blockIdx.x * blockDim.x + threadIdx.x) >> 5;
    int lane = threadIdx.x & 31;
    if (warp >= TOTROWS) return;
    int i = warp;
    int s, dd, kidx;
    if (i < EE) { s = ei[i]; dd = ei[EE + i]; kidx = i >> 10; }
    else { int n = i - EE; s = n; dd = n; kidx = BB + ntp[n]; }
    const float* kadd = &d_UKall[kidx * DD];
    const float* qrow = &d_XKMQ[(size_t)s * 600 + 400];
    const float* krow = &d_XKMQ[(size_t)dd * 600];
    const float invs = 0.1414213562373095f;
    int h = lane >> 3, r = lane & 7;
    float p = 0.f;
#pragma unroll
    for (int j = 0; j < 4; j++) {
        int idx = r + 8 * j;
        if (idx < 25) {
            int d0 = h * 50 + idx * 2;
            float2 q2  = *(const float2*)(qrow + d0);
            float2 k2  = *(const float2*)(krow + d0);
            float2 a2  = *(const float2*)(kadd + d0);
            float2 bq2 = *(const float2*)(bq + d0);
            float2 bk2 = *(const float2*)(bk + d0);
            p += ((q2.x + bq2.x) * invs) * (k2.x + a2.x + bk2.x)
               + ((q2.y + bq2.y) * invs) * (k2.y + a2.y + bk2.y);
        }
    }
    p += __shfl_down_sync(0xffffffffu, p, 4);
    p += __shfl_down_sync(0xffffffffu, p, 2);
    p += __shfl_down_sync(0xffffffffu, p, 1);
    if (r == 0) {
        float exv = __expf(p);
        d_ex[(size_t)i * 4 + h] = exv;
        atomicAdd(&d_den[s * 4 + h], exv);
    }
}

// ------------------------- aggregation via dst-CSR (atomic-free) -------------------------
__global__ __launch_bounds__(256) void k_D2csr(const int* __restrict__ ei,
                                               const int* __restrict__ ntp,
                                               const float* __restrict__ bm) {
    int n = blockIdx.x;
    int beg = d_dstOff[n], end = d_dstOff[n + 1];
    int tid = threadIdx.x;
    __shared__ float s_al[64][4];
    __shared__ int s_j[64];
    __shared__ int s_u[64];
    float acc = 0.f;
    float bmv = (tid < DD) ? bm[tid] : 0.f;
    int h = tid / 50;
    for (int base = beg; base < end; base += 64) {
        int cnt = min(64, end - base);
        __syncthreads();
        if (tid < cnt) {
            int i = d_csr[base + tid];
            int s, j, u;
            if (i < EE) { s = ei[i]; j = s; u = i >> 10; }
            else { int nn = i - EE; s = nn; j = nn; u = BB + ntp[nn]; }
            s_j[tid] = j;
            s_u[tid] = u;
            float cs = (float)d_cntSrc[s];
#pragma unroll
            for (int hh = 0; hh < 4; hh++)
                s_al[tid][hh] = d_ex[(size_t)i * 4 + hh] / d_den[s * 4 + hh] * cs;
        }
        __syncthreads();
        if (tid < DD) {
            for (int r = 0; r < cnt; r++) {
                const float* mrow = &d_XKMQ[(size_t)s_j[r] * 600 + 200];
                const float* urow = &d_UMall[s_u[r] * DD];
                acc += s_al[r][h] * (mrow[tid] + urow[tid] + bmv);
            }
        }
    }
    if (tid < DD) d_aggr[(size_t)n * DD + tid] = acc;
}

__global__ void k_stat3() {
    int d = threadIdx.x;
    if (d >= DD) return;
    float m = d_colsum[d] / (float)NN;
    float var = d_colsum2[d] / (float)NN - m * m;
    d_bn3m[d] = m;
    d_bn3r[d] = rsqrtf(var + 1e-5f);
}

// ------------------------- launch -------------------------
extern "C" void kernel_launch(void* const* d_in, const int* in_sizes, int n_in,
                              void* d_out, int out_size) {
    const float* x    = (const float*)d_in[0];
    const float* sent = (const float*)d_in[2];
    const float* We1  = (const float*)d_in[3];
    const float* be1  = (const float*)d_in[4];
    const float* ge1  = (const float*)d_in[5];
    const float* bte1 = (const float*)d_in[6];
    const float* We2  = (const float*)d_in[7];
    const float* be2  = (const float*)d_in[8];
    const float* Wa1  = (const float*)d_in[9];
    const float* ba1  = (const float*)d_in[10];
    const float* ga1  = (const float*)d_in[11];
    const float* bta1 = (const float*)d_in[12];
    const float* Wa2  = (const float*)d_in[13];
    const float* ba2  = (const float*)d_in[14];
    const float* Watt = (const float*)d_in[15];
    const float* Wk   = (const float*)d_in[16];
    const float* bk   = (const float*)d_in[17];
    const float* Wm   = (const float*)d_in[18];
    const float* bm   = (const float*)d_in[19];
    const float* Wq   = (const float*)d_in[20];
    const float* bq   = (const float*)d_in[21];
    const float* Wo1  = (const float*)d_in[22];
    const float* bo1  = (const float*)d_in[23];
    const float* go1  = (const float*)d_in[24];
    const float* bto1 = (const float*)d_in[25];
    const float* Wo2  = (const float*)d_in[26];
    const float* bo2  = (const float*)d_in[27];
    const int* ei     = (const int*)d_in[28];
    const int* et     = (const int*)d_in[29];
    const int* ntp    = (const int*)d_in[30];
    float* out = (float*)d_out;

    void* tmp;
    cudaGetSymbolAddress(&tmp, d_Wcat);  float* pWcat = (float*)tmp;
    cudaGetSymbolAddress(&tmp, d_Wo1P);  float* pWo1P = (float*)tmp;
    cudaGetSymbolAddress(&tmp, d_Wo2P);  float* pWo2P = (float*)tmp;
    cudaGetSymbolAddress(&tmp, d_XKMQ);  float* pXKMQ = (float*)tmp;
    cudaGetSymbolAddress(&tmp, d_aggr);  float* pAggr = (float*)tmp;
    cudaGetSymbolAddress(&tmp, d_Y1);    float* pY1   = (float*)tmp;
    cudaGetSymbolAddress(&tmp, d_bn3m);  float* pb3m  = (float*)tmp;
    cudaGetSymbolAddress(&tmp, d_bn3r);  float* pb3r  = (float*)tmp;

    k_zero<<<1024, 256>>>();
    k_nodehist<<<NN / 256, 256>>>(ntp);
    k_edgehist<<<EE / 256, 256>>>(ei, et, ntp);
    k_scanA<<<50, 1024>>>();
    k_scanB<<<1, 64>>>();
    k_scanC<<<50, 1024>>>();
    k_csrfill<<<(TOTROWS + 255) / 256, 256>>>(ei);
    k_segsum3<<<400, 128>>>(x);
    k_meanT<<<(NT1 * DD + 255) / 256, 256>>>();
    k_tables<<<NCOMBO + NTY, 256>>>(We1, be1);
    k_bnstat1p<<<DD, 128>>>();
    k_emb<<<NCOMBO + NTY, 256>>>(We2, be2, ge1, bte1);
    k_h2pre<<<NCOMBO, 256>>>(Wa1, ba1);
    k_bnstat2p<<<DD, 128>>>();
    k_Rtab<<<NCOMBO, 256>>>(Wa2, ba2, ga1, bta1);
    k_q<<<BB, 256>>>(sent, Watt);
    k_P<<<BB, 256>>>();
    k_graphsm<<<BB, 256>>>();
    k_upd<<<BB, 256>>>();
    k_ukum<<<BB + NTY, 256>>>(Wk, Wm);
    k_wcat<<<(DD * 640 + 255) / 256, 256>>>(Wk, Wm, Wq);
    k_wpad<<<(DD * 256 + 255) / 256, 256>>>(Wo1, pWo1P);
    k_wpad<<<(DD * 256 + 255) / 256, 256>>>(Wo2, pWo2P);
    {   // XKMQ = x @ [Wk1|Wm1|Wq]  (51200 x 600 x 200), tf32 tensor cores
        dim3 g(5, NN / 128);
        k_gemmT<0><<<g, 256>>>(NN, 600, DD, x, DD, pWcat, 640, pXKMQ, 600,
                               nullptr, nullptr, nullptr, nullptr, nullptr);
    }
    k_D1<<<(TOTROWS + 7) / 8, 256>>>(ei, ntp, bq, bk);
    k_D2csr<<<NN, 256>>>(ei, ntp, bm);
    {   // Y1 = aggr @ Wo1 + bo1  (+ fused column stats)
        dim3 g(2, NN / 128);
        k_gemmT<1><<<g, 256>>>(NN, DD, DD, pAggr, DD, pWo1P, 256, pY1, DD,
                               bo1, nullptr, nullptr, nullptr, nullptr);
    }
    k_stat3<<<1, 256>>>();
    {   // out = relu(bn(Y1)) @ Wo2 + bo2
        dim3 g(2, NN / 128);
        k_gemmT<0><<<g, 256>>>(NN, DD, DD, pY1, DD, pWo2P, 256, out, DD,
                               bo2, pb3m, pb3r, go1, bto1);
    }
}

// round 6
// speedup vs baseline: 2.5183x; 1.2219x over previous
#include <cuda_runtime.h>
#include <math.h>
#include <stdint.h>

#define DD 200
#define NTY 4
#define NET 38
#define NT1 39
#define BB 256
#define LL 1024
#define EE 262144
#define NN 51200
#define NCOMBO 608
#define TOTROWS (EE + NN)

// f32x2 packed-math helpers
#define FMA2(d,a,b)  asm("fma.rn.f32x2 %0, %1, %2, %3;" : "=l"(d) : "l"(a), "l"(b), "l"(d))
#define PACK2(d,x,y) asm("mov.b64 %0, {%1, %2};" : "=l"(d) : "f"(x), "f"(y))
#define UNPACK2(x,y,d) asm("mov.b64 {%0, %1}, %2;" : "=f"(x), "=f"(y) : "l"(d))

#define CVT_TF32(u,f) asm("cvt.rna.tf32.f32 %0, %1;" : "=r"(u) : "f"(f))
#define MMA_TF32(c0,c1,c2,c3,a0,a1,a2,a3,b0,b1) \
  asm("mma.sync.aligned.m16n8k8.row.col.f32.tf32.tf32.f32 " \
      "{%0,%1,%2,%3},{%4,%5,%6,%7},{%8,%9},{%0,%1,%2,%3};" \
      : "+f"(c0),"+f"(c1),"+f"(c2),"+f"(c3) \
      : "r"(a0),"r"(a1),"r"(a2),"r"(a3),"r"(b0),"r"(b1))

// ------------------------- scratch -------------------------
__device__ float d_coeff[(size_t)NN * NT1];
__device__ float d_sums[NT1 * DD];
__device__ int   d_cntT[NT1];
__device__ int   d_cntE[NCOMBO];
__device__ int   d_cntN[NTY];
__device__ int   d_combo[EE];
__device__ int   d_cntSrc[NN];
__device__ int   d_dstCnt[NN];
__device__ int   d_dstOff[NN + 1];
__device__ int   d_cursor[NN];
__device__ int   d_csr[TOTROWS];
__device__ int   d_blkSum[50];
__device__ float d_meanT[NT1 * DD];
__device__ float d_preE[NCOMBO * DD];
__device__ float d_preS[NTY * DD];
__device__ float d_embE[NCOMBO * DD];
__device__ float d_embS[NTY * DD];
__device__ float d_h2[NCOMBO * DD];
__device__ float d_Rtab[NCOMBO * DD];
__device__ float d_bn1m[DD], d_bn1r[DD], d_bn2m[DD], d_bn2r[DD], d_bn3m[DD], d_bn3r[DD];
__device__ float d_upd[BB * DD];
__device__ float d_UKall[(BB + NTY) * DD];
__device__ float d_UMall[(BB + NTY) * DD];
__device__ float d_Wcat[DD * 640];
__device__ float d_bcat[640];
__device__ float d_Wo1P[DD * 256];
__device__ float d_Wo2P[DD * 256];
__device__ float d_XKMQ[(size_t)NN * 600];    // per-node [XK+bk | XM+bm | (XQ+bq)*invs]
__device__ float d_ex[(size_t)TOTROWS * 4];
__device__ float d_den[NN * 4];
__device__ float d_aggr[(size_t)NN * DD];
__device__ float d_Y1[(size_t)NN * DD];
__device__ float d_colsum[DD], d_colsum2[DD];

// ------------------------- zero init + node hist (fused) -------------------------
__global__ void k_zero(const int* __restrict__ ntp) {
    long long i0 = (long long)blockIdx.x * blockDim.x + threadIdx.x;
    long long st = (long long)gridDim.x * blockDim.x;
    for (long long i = i0; i < (long long)NT1 * NN; i += st) d_coeff[i] = 0.f;
    for (long long i = i0; i < (long long)NN * 4; i += st) d_den[i] = 0.f;
    for (long long i = i0; i < NT1 * DD; i += st) d_sums[i] = 0.f;
    for (long long i = i0; i < NCOMBO; i += st) d_cntE[i] = 0;
    for (long long i = i0; i < NT1; i += st) d_cntT[i] = 0;
    for (long long i = i0; i < NTY; i += st) d_cntN[i] = 0;
    for (long long i = i0; i < DD; i += st) { d_colsum[i] = 0.f; d_colsum2[i] = 0.f; }
    for (long long i = i0; i < NN; i += st) {
        d_cntSrc[i] = 1;
        d_dstCnt[i] = 1;
        atomicAdd(&d_cntN[ntp[i]], 1);
    }
}

__global__ void k_edgehist(const int* __restrict__ ei, const int* __restrict__ et,
                           const int* __restrict__ ntp) {
    int e = blockIdx.x * blockDim.x + threadIdx.x;
    if (e >= EE) return;
    int s  = ei[e];
    int dd = ei[EE + e];
    int t  = et[e];
    atomicAdd(&d_coeff[(size_t)dd * NT1 + t],  1.f);
    atomicAdd(&d_coeff[(size_t)s  * NT1 + t], -1.f);
    atomicAdd(&d_cntT[t], 1);
    int c = (t << 4) | (ntp[s] << 2) | ntp[dd];
    d_combo[e] = c;
    atomicAdd(&d_cntE[c], 1);
    atomicAdd(&d_cntSrc[s], 1);
    atomicAdd(&d_dstCnt[dd], 1);
}

// ------------------------- dst-CSR build -------------------------
__global__ void k_scanA() {
    __shared__ int sm[1024];
    int tid = threadIdx.x;
    sm[tid] = d_dstCnt[blockIdx.x * 1024 + tid];
    __syncthreads();
    for (int o = 512; o > 0; o >>= 1) {
        if (tid < o) sm[tid] += sm[tid + o];
        __syncthreads();
    }
    if (tid == 0) d_blkSum[blockIdx.x] = sm[0];
}

__global__ void k_scanB() {
    __shared__ int sm[64];
    int tid = threadIdx.x;
    int v = (tid < 50) ? d_blkSum[tid] : 0;
    sm[tid] = v;
    __syncthreads();
    for (int o = 1; o < 64; o <<= 1) {
        int t = (tid >= o) ? sm[tid - o] : 0;
        __syncthreads();
        sm[tid] += t;
        __syncthreads();
    }
    if (tid < 50) d_blkSum[tid] = sm[tid] - v;
    if (tid == 49) d_dstOff[NN] = sm[49];
}

__global__ void k_scanC() {
    __shared__ int sm[1024];
    int tid = threadIdx.x;
    int g = blockIdx.x * 1024 + tid;
    int v = d_dstCnt[g];
    sm[tid] = v;
    __syncthreads();
    for (int o = 1; o < 1024; o <<= 1) {
        int t = (tid >= o) ? sm[tid - o] : 0;
        __syncthreads();
        sm[tid] += t;
        __syncthreads();
    }
    int excl = sm[tid] - v + d_blkSum[blockIdx.x];
    d_dstOff[g] = excl;
    d_cursor[g] = excl;
}

__global__ void k_csrfill(const int* __restrict__ ei) {
    int i = blockIdx.x * blockDim.x + threadIdx.x;
    if (i >= TOTROWS) return;
    int dst = (i < EE) ? ei[EE + i] : (i - EE);
    int pos = atomicAdd(&d_cursor[dst], 1);
    d_csr[pos] = i;
}

// ------------------------- segment sums -------------------------
__global__ __launch_bounds__(128) void k_segsum3(const float* __restrict__ x) {
    __shared__ unsigned long long cf2[128][NT1];
    int tid = threadIdx.x;
    int n0 = blockIdx.x * 128;
    for (int i = tid; i < 128 * NT1; i += 128) {
        float c = d_coeff[(size_t)(n0 + i / NT1) * NT1 + (i % NT1)];
        unsigned long long c2; PACK2(c2, c, c);
        cf2[i / NT1][i % NT1] = c2;
    }
    __syncthreads();
    if (tid < 100) {
        unsigned long long acc[NT1];
#pragma unroll
        for (int t = 0; t < NT1; t++) acc[t] = 0ULL;
        for (int nn = 0; nn < 128; nn++) {
            float2 xv = *(const float2*)&x[(size_t)(n0 + nn) * DD + tid * 2];
            unsigned long long xv2; PACK2(xv2, xv.x, xv.y);
#pragma unroll
            for (int t = 0; t < NT1; t++)
                FMA2(acc[t], cf2[nn][t], xv2);
        }
#pragma unroll
        for (int t = 0; t < NT1; t++) {
            float lo, hi; UNPACK2(lo, hi, acc[t]);
            if (lo != 0.f) atomicAdd(&d_sums[t * DD + tid * 2], lo);
            if (hi != 0.f) atomicAdd(&d_sums[t * DD + tid * 2 + 1], hi);
        }
    }
}

__global__ void k_meanT() {
    int i = blockIdx.x * blockDim.x + threadIdx.x;
    if (i >= NT1 * DD) return;
    int t = i / DD;
    float c = (float)d_cntT[t];
    if (c < 1.f) c = 1.f;
    d_meanT[i] = d_sums[i] / c;
}

// ------------------------- combo tables -------------------------
__global__ void k_tables(const float* __restrict__ We1, const float* __restrict__ be1) {
    int c = blockIdx.x, d = threadIdx.x;
    if (d >= DD) return;
    if (c < NCOMBO) {
        int t = c >> 4, a = (c >> 2) & 3, b = c & 3;
        d_preE[c * DD + d] = We1[t * DD + d] + We1[(NT1 + a) * DD + d]
                           + We1[(NT1 + NTY + b) * DD + d] + be1[d];
    } else {
        int t = c - NCOMBO;
        d_preS[t * DD + d] = We1[NET * DD + d] + We1[(NT1 + t) * DD + d]
                           + We1[(NT1 + NTY + t) * DD + d] + be1[d];
    }
}

__global__ void k_bnstat1p() {
    int d = blockIdx.x, tid = threadIdx.x;
    __shared__ double rs[128], rs2[128];
    double s = 0.0, s2 = 0.0;
    for (int c = tid; c < NCOMBO; c += 128) {
        double w = (double)d_cntE[c], v = (double)d_preE[c * DD + d];
        s += w * v; s2 += w * v * v;
    }
    if (tid < NTY) {
        double w = (double)d_cntN[tid], v = (double)d_preS[tid * DD + d];
        s += w * v; s2 += w * v * v;
    }
    rs[tid] = s; rs2[tid] = s2;
    __syncthreads();
    for (int o = 64; o > 0; o >>= 1) {
        if (tid < o) { rs[tid] += rs[tid + o]; rs2[tid] += rs2[tid + o]; }
        __syncthreads();
    }
    if (tid == 0) {
        double m = rs[0] / (double)TOTROWS;
        double var = rs2[0] / (double)TOTROWS - m * m;
        d_bn1m[d] = (float)m;
        d_bn1r[d] = rsqrtf((float)var + 1e-5f);
    }
}

__global__ void k_emb(const float* __restrict__ We2, const float* __restrict__ be2,
                      const float* __restrict__ g, const float* __restrict__ bt) {
    int c = blockIdx.x, d = threadIdx.x;
    __shared__ float a[DD];
    const float* srow = (c < NCOMBO) ? &d_preE[c * DD] : &d_preS[(c - NCOMBO) * DD];
    if (d < DD) {
        float v = (srow[d] - d_bn1m[d]) * d_bn1r[d] * g[d] + bt[d];
        a[d] = fmaxf(v, 0.f);
    }
    __syncthreads();
    if (d < DD) {
        float acc = 0.f;
        for (int k = 0; k < DD; k++) acc += a[k] * We2[k * DD + d];
        float* dst = (c < NCOMBO) ? &d_embE[c * DD] : &d_embS[(c - NCOMBO) * DD];
        dst[d] = acc + be2[d];
    }
}

__global__ void k_h2pre(const float* __restrict__ Wa1, const float* __restrict__ ba1) {
    int c = blockIdx.x, d = threadIdx.x;
    __shared__ float e[DD], mt[DD];
    int t = c >> 4;
    if (d < DD) { e[d] = d_embE[c * DD + d]; mt[d] = d_meanT[t * DD + d]; }
    __syncthreads();
    if (d < DD) {
        float acc = ba1[d];
        for (int k = 0; k < DD; k++) acc += e[k] * Wa1[k * DD + d];
        for (int k = 0; k < DD; k++) acc += mt[k] * Wa1[(DD + k) * DD + d];
        d_h2[c * DD + d] = acc;
    }
}

__global__ void k_bnstat2p() {
    int d = blockIdx.x, tid = threadIdx.x;
    __shared__ double rs[128], rs2[128];
    double s = 0.0, s2 = 0.0;
    for (int c = tid; c < NCOMBO; c += 128) {
        double w = (double)d_cntE[c], v = (double)d_h2[c * DD + d];
        s += w * v; s2 += w * v * v;
    }
    rs[tid] = s; rs2[tid] = s2;
    __syncthreads();
    for (int o = 64; o > 0; o >>= 1) {
        if (tid < o) { rs[tid] += rs[tid + o]; rs2[tid] += rs2[tid + o]; }
        __syncthreads();
    }
    if (tid == 0) {
        double m = rs[0] / (double)EE;
        double var = rs2[0] / (double)EE - m * m;
        d_bn2m[d] = (float)m;
        d_bn2r[d] = rsqrtf((float)var + 1e-5f);
    }
}

__global__ void k_Rtab(const float* __restrict__ Wa2, const float* __restrict__ ba2,
                       const float* __restrict__ g, const float* __restrict__ bt) {
    int c = blockIdx.x, d = threadIdx.x;
    __shared__ float a[DD];
    if (d < DD) {
        float v = (d_h2[c * DD + d] - d_bn2m[d]) * d_bn2r[d] * g[d] + bt[d];
        a[d] = fmaxf(v, 0.f);
    }
    __syncthreads();
    if (d < DD) {
        float acc = 0.f;
        for (int k = 0; k < DD; k++) acc += a[k] * Wa2[k * DD + d];
        d_Rtab[c * DD + d] = acc + ba2[d];
    }
}

// ------------------------- fused graph attention: q, P, softmax, upd -------------------------
__global__ __launch_bounds__(256) void k_attn(const float* __restrict__ sent,
                                              const float* __restrict__ Watt) {
    int b = blockIdx.x, tid = threadIdx.x;
    __shared__ float sv[DD], q[DD];
    __shared__ float Pb[NCOMBO], Wacc[NCOMBO];
    __shared__ float red[256];
    if (tid < DD) sv[tid] = sent[b * DD + tid];
    for (int i = tid; i < NCOMBO; i += 256) Wacc[i] = 0.f;
    __syncthreads();
    if (tid < DD) {
        float a = 0.f;
        for (int k = 0; k < DD; k++) a += sv[k] * Watt[k * DD + tid];
        q[tid] = a * 0.07071067811865475f;   // 1/sqrt(200)
    }
    __syncthreads();
    int lane = tid & 31, w = tid >> 5;
    for (int c = w; c < NCOMBO; c += 8) {
        float p = 0.f;
        for (int k = lane; k < DD; k += 32) p += q[k] * d_Rtab[c * DD + k];
        for (int o = 16; o > 0; o >>= 1) p += __shfl_down_sync(0xffffffffu, p, o);
        if (lane == 0) Pb[c] = p;
    }
    __syncthreads();
    int cid[4]; float sc[4]; float lmax = -1e30f;
#pragma unroll
    for (int j = 0; j < 4; j++) {
        int e = b * LL + tid + j * 256;
        cid[j] = d_combo[e];
        sc[j] = Pb[cid[j]];
        lmax = fmaxf(lmax, sc[j]);
    }
    red[tid] = lmax; __syncthreads();
    for (int s = 128; s > 0; s >>= 1) { if (tid < s) red[tid] = fmaxf(red[tid], red[tid + s]); __syncthreads(); }
    float bmax = red[0]; __syncthreads();
    float lsum = 0.f;
#pragma unroll
    for (int j = 0; j < 4; j++) { sc[j] = expf(sc[j] - bmax); lsum += sc[j]; }
    red[tid] = lsum; __syncthreads();
    for (int s = 128; s > 0; s >>= 1) { if (tid < s) red[tid] += red[tid + s]; __syncthreads(); }
    float inv = 1.f / red[0]; __syncthreads();
#pragma unroll
    for (int j = 0; j < 4; j++) atomicAdd(&Wacc[cid[j]], sc[j] * inv);
    __syncthreads();
    if (tid < DD) {
        float a = 0.f;
        for (int c = 0; c < NCOMBO; c++) a += Wacc[c] * d_Rtab[c * DD + tid];
        d_upd[b * DD + tid] = a;
    }
}

__global__ void k_ukum(const float* __restrict__ Wk, const float* __restrict__ Wm) {
    int id = blockIdx.x, d = threadIdx.x;
    __shared__ float s[DD];
    const float* srow = (id < BB) ? &d_upd[id * DD] : &d_embS[(id - BB) * DD];
    if (d < DD) s[d] = srow[d];
    __syncthreads();
    if (d < DD) {
        float ak = 0.f, am = 0.f;
        for (int k = 0; k < DD; k++) {
            float sv = s[k];
            ak += sv * Wk[(DD + k) * DD + d];
            am += sv * Wm[(DD + k) * DD + d];
        }
        d_UKall[id * DD + d] = ak;
        d_UMall[id * DD + d] = am;
    }
}

// ------------------------- fused weight packing -------------------------
// Wcat cols: [Wk1 | Wm1 | Wq*invs | 0pad]; bcat: [bk | bm | bq*invs | 0pad]; Wo1P/Wo2P pad to 256.
__global__ void k_pack(const float* __restrict__ Wk, const float* __restrict__ Wm,
                       const float* __restrict__ Wq,
                       const float* __restrict__ bk, const float* __restrict__ bm,
                       const float* __restrict__ bq,
                       const float* __restrict__ Wo1, const float* __restrict__ Wo2) {
    const float invs = 0.1414213562373095f;   // 1/sqrt(50)
    int i = blockIdx.x * blockDim.x + threadIdx.x;
    if (i < DD * 640) {
        int k = i / 640, c = i % 640;
        float v = (c < DD) ? Wk[k * DD + c]
                : (c < 2 * DD) ? Wm[k * DD + (c - DD)]
                : (c < 3 * DD) ? Wq[k * DD + (c - 2 * DD)] * invs : 0.f;
        d_Wcat[i] = v;
        return;
    }
    int j = i - DD * 640;
    if (j < DD * 256) {
        int k = j >> 8, c = j & 255;
        d_Wo1P[j] = (c < DD) ? Wo1[k * DD + c] : 0.f;
        return;
    }
    j -= DD * 256;
    if (j < DD * 256) {
        int k = j >> 8, c = j & 255;
        d_Wo2P[j] = (c < DD) ? Wo2[k * DD + c] : 0.f;
        return;
    }
    j -= DD * 256;
    if (j < 640) {
        float v = (j < DD) ? bk[j]
                : (j < 2 * DD) ? bm[j - DD]
                : (j < 3 * DD) ? bq[j - 2 * DD] * invs : 0.f;
        d_bcat[j] = v;
    }
}

// ------------------------- tf32 GEMM: 128x128 tile, 2-stage smem pipeline -------------------------
template<int DOSTAT>
__global__ __launch_bounds__(256, 2) void k_gemmT(
    int M, int Nreal, int K,
    const float* __restrict__ A, int lda,
    const float* __restrict__ B, int ldb,
    float* __restrict__ C, int ldc,
    const float* __restrict__ bias,
    const float* __restrict__ bnm, const float* __restrict__ bnr,
    const float* __restrict__ bng, const float* __restrict__ bnb) {
    __shared__ uint32_t As[2][8][132];
    __shared__ uint32_t Bs[2][8][132];
    __shared__ float cs[128], cs2[128];
    int tid = threadIdx.x;
    int lane = tid & 31, warp = tid >> 5;
    int wm = warp >> 2, wn = warp & 3;
    int gid = lane >> 2, tg = lane & 3;
    int row0 = blockIdx.y * 128, col0 = blockIdx.x * 128;
    if (DOSTAT && tid < 128) { cs[tid] = 0.f; cs2[tid] = 0.f; }

    float acc[4][4][4];
#pragma unroll
    for (int mt = 0; mt < 4; mt++)
#pragma unroll
        for (int nt = 0; nt < 4; nt++)
#pragma unroll
            for (int r = 0; r < 4; r++) acc[mt][nt][r] = 0.f;

    int rowA = row0 + (tid >> 1);
    int kA = (tid & 1) * 4;
    int rowB = tid >> 5;
    int colB = (tid & 31) * 4;
    int m0 = wm * 64, n0 = wn * 32;
    int mrow = tid >> 1;
    int nk = K / 8;   // 25

    float4 av, bv;
    // prologue: load + store tile 0 into stage 0
    {
        av = *(const float4*)&A[(size_t)rowA * lda + kA];
        if (bnm) {
            int g = kA;
            av.x = fmaxf((av.x - bnm[g])     * bnr[g]     * bng[g]     + bnb[g],     0.f);
            av.y = fmaxf((av.y - bnm[g + 1]) * bnr[g + 1] * bng[g + 1] + bnb[g + 1], 0.f);
            av.z = fmaxf((av.z - bnm[g + 2]) * bnr[g + 2] * bng[g + 2] + bnb[g + 2], 0.f);
            av.w = fmaxf((av.w - bnm[g + 3]) * bnr[g + 3] * bng[g + 3] + bnb[g + 3], 0.f);
        }
        bv = *(const float4*)&B[(size_t)rowB * ldb + col0 + colB];
        uint32_t u0, u1, u2, u3;
        CVT_TF32(u0, av.x); CVT_TF32(u1, av.y); CVT_TF32(u2, av.z); CVT_TF32(u3, av.w);
        As[0][kA + 0][mrow] = u0; As[0][kA + 1][mrow] = u1;
        As[0][kA + 2][mrow] = u2; As[0][kA + 3][mrow] = u3;
        CVT_TF32(u0, bv.x); CVT_TF32(u1, bv.y); CVT_TF32(u2, bv.z); CVT_TF32(u3, bv.w);
        Bs[0][rowB][colB] = u0; Bs[0][rowB][colB + 1] = u1;
        Bs[0][rowB][colB + 2] = u2; Bs[0][rowB][colB + 3] = u3;
    }

    for (int kt = 0; kt < nk; kt++) {
        int cur = kt & 1;
        int nxt = cur ^ 1;
        bool has = (kt + 1 < nk);
        if (has) {
            int k0 = (kt + 1) * 8;
            av = *(const float4*)&A[(size_t)rowA * lda + k0 + kA];
            if (bnm) {
                int g = k0 + kA;
                av.x = fmaxf((av.x - bnm[g])     * bnr[g]     * bng[g]     + bnb[g],     0.f);
                av.y = fmaxf((av.y - bnm[g + 1]) * bnr[g + 1] * bng[g + 1] + bnb[g + 1], 0.f);
                av.z = fmaxf((av.z - bnm[g + 2]) * bnr[g + 2] * bng[g + 2] + bnb[g + 2], 0.f);
                av.w = fmaxf((av.w - bnm[g + 3]) * bnr[g + 3] * bng[g + 3] + bnb[g + 3], 0.f);
            }
            bv = *(const float4*)&B[(size_t)(k0 + rowB) * ldb + col0 + colB];
        }
        __syncthreads();   // stage `cur` visible; all mma on `nxt` (iter kt-1) done
        if (has) {
            uint32_t u0, u1, u2, u3;
            CVT_TF32(u0, av.x); CVT_TF32(u1, av.y); CVT_TF32(u2, av.z); CVT_TF32(u3, av.w);
            As[nxt][kA + 0][mrow] = u0; As[nxt][kA + 1][mrow] = u1;
            As[nxt][kA + 2][mrow] = u2; As[nxt][kA + 3][mrow] = u3;
            CVT_TF32(u0, bv.x); CVT_TF32(u1, bv.y); CVT_TF32(u2, bv.z); CVT_TF32(u3, bv.w);
            Bs[nxt][rowB][colB] = u0; Bs[nxt][rowB][colB + 1] = u1;
            Bs[nxt][rowB][colB + 2] = u2; Bs[nxt][rowB][colB + 3] = u3;
        }
        uint32_t af[4][4], bf[4][2];
#pragma unroll
        for (int mt = 0; mt < 4; mt++) {
            int mb = m0 + mt * 16 + gid;
            af[mt][0] = As[cur][tg][mb];
            af[mt][1] = As[cur][tg][mb + 8];
            af[mt][2] = As[cur][tg + 4][mb];
            af[mt][3] = As[cur][tg + 4][mb + 8];
        }
#pragma unroll
        for (int nt = 0; nt < 4; nt++) {
            int nb = n0 + nt * 8 + gid;
            bf[nt][0] = Bs[cur][tg][nb];
            bf[nt][1] = Bs[cur][tg + 4][nb];
        }
#pragma unroll
        for (int mt = 0; mt < 4; mt++)
#pragma unroll
            for (int nt = 0; nt < 4; nt++)
                MMA_TF32(acc[mt][nt][0], acc[mt][nt][1], acc[mt][nt][2], acc[mt][nt][3],
                         af[mt][0], af[mt][1], af[mt][2], af[mt][3],
                         bf[nt][0], bf[nt][1]);
    }

    float colS[4][2], colS2[4][2];
#pragma unroll
    for (int nt = 0; nt < 4; nt++) { colS[nt][0] = colS[nt][1] = 0.f; colS2[nt][0] = colS2[nt][1] = 0.f; }
#pragma unroll
    for (int mt = 0; mt < 4; mt++) {
        int r = row0 + m0 + mt * 16 + gid;
#pragma unroll
        for (int nt = 0; nt < 4; nt++) {
            int c = col0 + n0 + nt * 8 + tg * 2;
            float b0 = (bias && c < Nreal)     ? bias[c]     : 0.f;
            float b1 = (bias && c + 1 < Nreal) ? bias[c + 1] : 0.f;
            float v0 = acc[mt][nt][0] + b0;
            float v1 = acc[mt][nt][1] + b1;
            float v2 = acc[mt][nt][2] + b0;
            float v3 = acc[mt][nt][3] + b1;
            float* cr0 = &C[(size_t)r * ldc];
            float* cr1 = &C[(size_t)(r + 8) * ldc];
            if (c < Nreal)     { cr0[c] = v0; cr1[c] = v2; }
            if (c + 1 < Nreal) { cr0[c + 1] = v1; cr1[c + 1] = v3; }
            if (DOSTAT) {
                colS[nt][0]  += v0 + v2;
                colS2[nt][0] += v0 * v0 + v2 * v2;
                colS[nt][1]  += v1 + v3;
                colS2[nt][1] += v1 * v1 + v3 * v3;
            }
        }
    }
    if (DOSTAT) {
#pragma unroll
        for (int nt = 0; nt < 4; nt++) {
#pragma unroll
            for (int p = 0; p < 2; p++) {
                float a = colS[nt][p], b = colS2[nt][p];
                for (int o = 16; o >= 4; o >>= 1) {
                    a += __shfl_down_sync(0xffffffffu, a, o);
                    b += __shfl_down_sync(0xffffffffu, b, o);
                }
                colS[nt][p] = a; colS2[nt][p] = b;
            }
        }
        __syncthreads();
        if (gid == 0) {
#pragma unroll
            for (int nt = 0; nt < 4; nt++) {
                int lc = n0 + nt * 8 + tg * 2;
                atomicAdd(&cs[lc],      colS[nt][0]);
                atomicAdd(&cs2[lc],     colS2[nt][0]);
                atomicAdd(&cs[lc + 1],  colS[nt][1]);
                atomicAdd(&cs2[lc + 1], colS2[nt][1]);
            }
        }
        __syncthreads();
        if (tid < 128) {
            int gc = col0 + tid;
            if (gc < Nreal) {
                atomicAdd(&d_colsum[gc],  cs[tid]);
                atomicAdd(&d_colsum2[gc], cs2[tid]);
            }
        }
    }
}

// ------------------------- edge attention: scores + softmax denominators -------------------------
// Biases and 1/sqrt(50) pre-folded into XKMQ via GEMM bias / scaled Wq.
__global__ void k_D1(const int* __restrict__ ei, const int* __restrict__ ntp) {
    int warp = (blockIdx.x * blockDim.x + threadIdx.x) >> 5;
    int lane = threadIdx.x & 31;
    if (warp >= TOTROWS) return;
    int i = warp;
    int s, dd, kidx;
    if (i < EE) { s = ei[i]; dd = ei[EE + i]; kidx = i >> 10; }
    else { int n = i - EE; s = n; dd = n; kidx = BB + ntp[n]; }
    const float* kadd = &d_UKall[kidx * DD];
    const float* qrow = &d_XKMQ[(size_t)s * 600 + 400];
    const float* krow = &d_XKMQ[(size_t)dd * 600];
    int h = lane >> 3, r = lane & 7;
    float p = 0.f;
#pragma unroll
    for (int j = 0; j < 4; j++) {
        int idx = r + 8 * j;
        if (idx < 25) {
            int d0 = h * 50 + idx * 2;
            float2 q2 = *(const float2*)(qrow + d0);
            float2 k2 = *(const float2*)(krow + d0);
            float2 a2 = *(const float2*)(kadd + d0);
            p += q2.x * (k2.x + a2.x) + q2.y * (k2.y + a2.y);
        }
    }
    p += __shfl_down_sync(0xffffffffu, p, 4);
    p += __shfl_down_sync(0xffffffffu, p, 2);
    p += __shfl_down_sync(0xffffffffu, p, 1);
    if (r == 0) {
        float exv = __expf(p);
        d_ex[(size_t)i * 4 + h] = exv;
        atomicAdd(&d_den[s * 4 + h], exv);
    }
}

// ------------------------- aggregation: one warp per dst node -------------------------
__global__ __launch_bounds__(256) void k_D2w(const int* __restrict__ ei,
                                             const int* __restrict__ ntp) {
    int gw = (blockIdx.x * blockDim.x + threadIdx.x) >> 5;
    int lane = threadIdx.x & 31;
    int w = threadIdx.x >> 5;
    if (gw >= NN) return;
    int n = gw;
    int beg = d_dstOff[n], end = d_dstOff[n + 1];
    __shared__ float s_al[8][16][4];
    __shared__ int s_j[8][16], s_u[8][16];
    float acc[7];
#pragma unroll
    for (int k = 0; k < 7; k++) acc[k] = 0.f;
    for (int base = beg; base < end; base += 16) {
        int cnt = min(16, end - base);
        if (lane < cnt) {
            int i = d_csr[base + lane];
            int s, j, u;
            if (i < EE) { s = ei[i]; j = s; u = i >> 10; }
            else { int nn2 = i - EE; s = nn2; j = nn2; u = BB + ntp[nn2]; }
            s_j[w][lane] = j;
            s_u[w][lane] = u;
            float csf = (float)d_cntSrc[s];
#pragma unroll
            for (int hh = 0; hh < 4; hh++)
                s_al[w][lane][hh] = __fdividef(d_ex[(size_t)i * 4 + hh], d_den[s * 4 + hh]) * csf;
        }
        __syncwarp();
        for (int r = 0; r < cnt; r++) {
            const float* mrow = &d_XKMQ[(size_t)s_j[w][r] * 600 + 200];
            const float* urow = &d_UMall[s_u[w][r] * DD];
            float a0 = s_al[w][r][0], a1 = s_al[w][r][1];
            float a2 = s_al[w][r][2], a3 = s_al[w][r][3];
#pragma unroll
            for (int k = 0; k < 7; k++) {
                int c = lane + 32 * k;
                if (c < DD) {
                    float al = c < 50 ? a0 : c < 100 ? a1 : c < 150 ? a2 : a3;
                    acc[k] += al * (mrow[c] + urow[c]);
                }
            }
        }
        __syncwarp();
    }
#pragma unroll
    for (int k = 0; k < 7; k++) {
        int c = lane + 32 * k;
        if (c < DD) d_aggr[(size_t)n * DD + c] = acc[k];
    }
}

__global__ void k_stat3() {
    int d = threadIdx.x;
    if (d >= DD) return;
    float m = d_colsum[d] / (float)NN;
    float var = d_colsum2[d] / (float)NN - m * m;
    d_bn3m[d] = m;
    d_bn3r[d] = rsqrtf(var + 1e-5f);
}

// ------------------------- launch -------------------------
extern "C" void kernel_launch(void* const* d_in, const int* in_sizes, int n_in,
                              void* d_out, int out_size) {
    const float* x    = (const float*)d_in[0];
    const float* sent = (const float*)d_in[2];
    const float* We1  = (const float*)d_in[3];
    const float* be1  = (const float*)d_in[4];
    const float* ge1  = (const float*)d_in[5];
    const float* bte1 = (const float*)d_in[6];
    const float* We2  = (const float*)d_in[7];
    const float* be2  = (const float*)d_in[8];
    const float* Wa1  = (const float*)d_in[9];
    const float* ba1  = (const float*)d_in[10];
    const float* ga1  = (const float*)d_in[11];
    const float* bta1 = (const float*)d_in[12];
    const float* Wa2  = (const float*)d_in[13];
    const float* ba2  = (const float*)d_in[14];
    const float* Watt = (const float*)d_in[15];
    const float* Wk   = (const float*)d_in[16];
    const float* bk   = (const float*)d_in[17];
    const float* Wm   = (const float*)d_in[18];
    const float* bm   = (const float*)d_in[19];
    const float* Wq   = (const float*)d_in[20];
    const float* bq   = (const float*)d_in[21];
    const float* Wo1  = (const float*)d_in[22];
    const float* bo1  = (const float*)d_in[23];
    const float* go1  = (const float*)d_in[24];
    const float* bto1 = (const float*)d_in[25];
    const float* Wo2  = (const float*)d_in[26];
    const float* bo2  = (const float*)d_in[27];
    const int* ei     = (const int*)d_in[28];
    const int* et     = (const int*)d_in[29];
    const int* ntp    = (const int*)d_in[30];
    float* out = (float*)d_out;

    void* tmp;
    cudaGetSymbolAddress(&tmp, d_Wcat);  float* pWcat = (float*)tmp;
    cudaGetSymbolAddress(&tmp, d_bcat);  float* pbcat = (float*)tmp;
    cudaGetSymbolAddress(&tmp, d_Wo1P);  float* pWo1P = (float*)tmp;
    cudaGetSymbolAddress(&tmp, d_Wo2P);  float* pWo2P = (float*)tmp;
    cudaGetSymbolAddress(&tmp, d_XKMQ);  float* pXKMQ = (float*)tmp;
    cudaGetSymbolAddress(&tmp, d_aggr);  float* pAggr = (float*)tmp;
    cudaGetSymbolAddress(&tmp, d_Y1);    float* pY1   = (float*)tmp;
    cudaGetSymbolAddress(&tmp, d_bn3m);  float* pb3m  = (float*)tmp;
    cudaGetSymbolAddress(&tmp, d_bn3r);  float* pb3r  = (float*)tmp;

    k_zero<<<1024, 256>>>(ntp);
    k_edgehist<<<EE / 256, 256>>>(ei, et, ntp);
    k_pack<<<(DD * 640 + 2 * DD * 256 + 640 + 255) / 256, 256>>>(Wk, Wm, Wq, bk, bm, bq, Wo1, Wo2);
    k_scanA<<<50, 1024>>>();
    k_scanB<<<1, 64>>>();
    k_scanC<<<50, 1024>>>();
    k_csrfill<<<(TOTROWS + 255) / 256, 256>>>(ei);
    k_segsum3<<<400, 128>>>(x);
    k_meanT<<<(NT1 * DD + 255) / 256, 256>>>();
    k_tables<<<NCOMBO + NTY, 256>>>(We1, be1);
    k_bnstat1p<<<DD, 128>>>();
    k_emb<<<NCOMBO + NTY, 256>>>(We2, be2, ge1, bte1);
    k_h2pre<<<NCOMBO, 256>>>(Wa1, ba1);
    k_bnstat2p<<<DD, 128>>>();
    k_Rtab<<<NCOMBO, 256>>>(Wa2, ba2, ga1, bta1);
    k_attn<<<BB, 256>>>(sent, Watt);
    k_ukum<<<BB + NTY, 256>>>(Wk, Wm);
    {   // XKMQ = x @ [Wk1|Wm1|Wq*invs] + [bk|bm|bq*invs]
        dim3 g(5, NN / 128);
        k_gemmT<0><<<g, 256>>>(NN, 600, DD, x, DD, pWcat, 640, pXKMQ, 600,
                               pbcat, nullptr, nullptr, nullptr, nullptr);
    }
    k_D1<<<(TOTROWS + 7) / 8, 256>>>(ei, ntp);
    k_D2w<<<NN / 8, 256>>>(ei, ntp);
    {   // Y1 = aggr @ Wo1 + bo1  (+ fused column stats)
        dim3 g(2, NN / 128);
        k_gemmT<1><<<g, 256>>>(NN, DD, DD, pAggr, DD, pWo1P, 256, pY1, DD,
                               bo1, nullptr, nullptr, nullptr, nullptr);
    }
    k_stat3<<<1, 256>>>();
    {   // out = relu(bn(Y1)) @ Wo2 + bo2
        dim3 g(2, NN / 128);
        k_gemmT<0><<<g, 256>>>(NN, DD, DD, pY1, DD, pWo2P, 256, out, DD,
                               bo2, pb3m, pb3r, go1, bto1);
    }
}